// round 13
// baseline (speedup 1.0000x reference)
#include <cuda_runtime.h>
#include <cuda_bf16.h>
#include <cstdint>

#define BB 2
#define SS 2048
#define DD 1024
#define HH 16
#define EHD 64
#define MM (BB*SS)   // 4096

// fp32 activations (tf32-rounded) for flash
__device__ float g_q[MM*DD];
__device__ float g_k[MM*DD];
__device__ float g_v[MM*DD];
// bf16 hi/lo split operands for the b3 GEMMs
__device__ __nv_bfloat16 g_e_hi[MM*DD],  g_e_lo[MM*DD];
__device__ __nv_bfloat16 g_o_hi[MM*DD],  g_o_lo[MM*DD];
__device__ __nv_bfloat16 g_w_hi[3*DD*DD], g_w_lo[3*DD*DD];   // Weff q,k,v
__device__ __nv_bfloat16 g_wo_hi[DD*DD],  g_wo_lo[DD*DD];

__device__ __forceinline__ uint32_t f2tf(float x) {
    uint32_t u; asm("cvt.rna.tf32.f32 %0, %1;" : "=r"(u) : "f"(x)); return u;
}

template<bool DOCVT>
__device__ __forceinline__ uint4 pack4(float4 v) {
    if (DOCVT)
        return make_uint4(f2tf(v.x), f2tf(v.y), f2tf(v.z), f2tf(v.w));
    return make_uint4(__float_as_uint(v.x), __float_as_uint(v.y),
                      __float_as_uint(v.z), __float_as_uint(v.w));
}

__device__ __forceinline__ uint32_t smem_u32(const void* p) {
    uint32_t a;
    asm("{ .reg .u64 t; cvta.to.shared.u64 t, %1; cvt.u32.u64 %0, t; }"
        : "=r"(a) : "l"(p));
    return a;
}

__device__ __forceinline__ void ldsm4(uint32_t* d, uint32_t addr) {
    asm volatile("ldmatrix.sync.aligned.m8n8.x4.shared.b16 {%0,%1,%2,%3}, [%4];"
        : "=r"(d[0]), "=r"(d[1]), "=r"(d[2]), "=r"(d[3]) : "r"(addr));
}

// tf32 m16n8k8
__device__ __forceinline__ void mma8(float* d, const uint32_t* a, const uint32_t* b) {
    asm volatile("mma.sync.aligned.m16n8k8.row.col.f32.tf32.tf32.f32 "
        "{%0,%1,%2,%3}, {%4,%5,%6,%7}, {%8,%9}, {%0,%1,%2,%3};\n"
        : "+f"(d[0]), "+f"(d[1]), "+f"(d[2]), "+f"(d[3])
        : "r"(a[0]), "r"(a[1]), "r"(a[2]), "r"(a[3]), "r"(b[0]), "r"(b[1]));
}

// bf16 m16n8k16
__device__ __forceinline__ void mma16(float* d, const uint32_t* a, const uint32_t* b) {
    asm volatile("mma.sync.aligned.m16n8k16.row.col.f32.bf16.bf16.f32 "
        "{%0,%1,%2,%3}, {%4,%5,%6,%7}, {%8,%9}, {%0,%1,%2,%3};\n"
        : "+f"(d[0]), "+f"(d[1]), "+f"(d[2]), "+f"(d[3])
        : "r"(a[0]), "r"(a[1]), "r"(a[2]), "r"(a[3]), "r"(b[0]), "r"(b[1]));
}

__device__ __forceinline__ void cp_async16(uint32_t saddr, const void* gaddr) {
    asm volatile("cp.async.ca.shared.global [%0], [%1], 16;"
                 :: "r"(saddr), "l"(gaddr) : "memory");
}
__device__ __forceinline__ void cp_commit() {
    asm volatile("cp.async.commit_group;" ::: "memory");
}

__device__ __forceinline__ float ex2(float x) {
    float r; asm("ex2.approx.f32 %0, %1;" : "=f"(r) : "f"(x)); return r;
}

__device__ __forceinline__ void split2(float x, __nv_bfloat16& h, __nv_bfloat16& l) {
    h = __float2bfloat16_rn(x);
    l = __float2bfloat16_rn(x - __bfloat162float(h));
}

// ---------------------------------------------------------------------------
// Elementwise bf16 hi/lo split producer
// ---------------------------------------------------------------------------
__global__ void split_bf16(const float* __restrict__ s,
                           __nv_bfloat16* __restrict__ hi,
                           __nv_bfloat16* __restrict__ lo, int n)
{
    int i = blockIdx.x * blockDim.x + threadIdx.x;
    if (i < n) {
        __nv_bfloat16 h, l;
        split2(s[i], h, l);
        hi[i] = h; lo[i] = l;
    }
}

// ---------------------------------------------------------------------------
// Weight-prep GEMM (NN, tf32 internals, R12-proven shape):
// Weff = HXcat[1024,1024] @ WX[1024,1024]; epilogue writes bf16 hi/lo split.
// 128 threads, warp tile 64x64 (2x2), CTA tile 128x128, BK=16, 2-stage buffer.
// ---------------------------------------------------------------------------
struct WBatch { const float* A[3]; const float* B[3]; };

__global__ __launch_bounds__(128) void gemm_nn_w(WBatch gb, int M, int N, int K)
{
    __shared__ uint32_t As[2][128][20];
    __shared__ uint32_t Bs[2][128][20];
    const float* __restrict__ A  = gb.A[blockIdx.z];
    const float* __restrict__ Bm = gb.B[blockIdx.z];
    __nv_bfloat16* __restrict__ Chi = g_w_hi + (size_t)blockIdx.z * DD * DD;
    __nv_bfloat16* __restrict__ Clo = g_w_lo + (size_t)blockIdx.z * DD * DD;

    const int tid  = threadIdx.x;
    const int lane = tid & 31, wid = tid >> 5;
    const int wm = wid & 1, wn = wid >> 1;
    const int m0 = blockIdx.y * 128, n0 = blockIdx.x * 128;
    const int r = lane >> 2, c = lane & 3;

    const int l15   = lane & 15;
    const int khalf = (lane >> 4) & 1;
    const int b_r   = (lane & 7) + ((lane & 16) >> 1);
    const int b_k4  = (lane & 8) >> 1;

    const uint32_t As_base = smem_u32(&As[0][0][0]);
    const uint32_t Bs_base = smem_u32(&Bs[0][0][0]);
    const uint32_t BUFB = 128 * 20 * 4;
    const uint32_t a_addr0 = As_base + (((wm * 64 + l15) * 20 + 4 * khalf) << 2);
    const uint32_t b_addr0 = Bs_base + (((wn * 64 + b_r) * 20 + b_k4) << 2);

    const int arow = tid >> 2, akq = (tid & 3) * 4;
    const int bkk  = tid & 15, bc4 = tid >> 4;

    float acc[4][8][4] = {};
    float4 pa[4], pb[4];

    auto ldg_tile = [&](int k0) {
#pragma unroll
        for (int i = 0; i < 4; i++)
            pa[i] = *(const float4*)&A[(size_t)(m0 + arow + 32 * i) * K + k0 + akq];
#pragma unroll
        for (int i = 0; i < 4; i++)
            pb[i] = *(const float4*)&Bm[(size_t)(k0 + bkk) * N + n0 + (bc4 + 8 * i) * 4];
    };
    auto sts_tile = [&](int buf) {
#pragma unroll
        for (int i = 0; i < 4; i++)
            *(uint4*)&As[buf][arow + 32 * i][akq] = pack4<true>(pa[i]);
#pragma unroll
        for (int i = 0; i < 4; i++) {
            uint4 u = pack4<true>(pb[i]);
            Bs[buf][(bc4 + 8 * i) * 4 + 0][bkk] = u.x;
            Bs[buf][(bc4 + 8 * i) * 4 + 1][bkk] = u.y;
            Bs[buf][(bc4 + 8 * i) * 4 + 2][bkk] = u.z;
            Bs[buf][(bc4 + 8 * i) * 4 + 3][bkk] = u.w;
        }
    };

    const int ntiles = K / 16;
    ldg_tile(0);
    sts_tile(0);
    if (ntiles > 1) ldg_tile(16);
    __syncthreads();

    for (int kt = 0; kt < ntiles; kt++) {
        const int buf = kt & 1;
        if (kt + 1 < ntiles) {
            sts_tile(buf ^ 1);
            if (kt + 2 < ntiles) ldg_tile((kt + 2) * 16);
        }

        const uint32_t aoff = buf ? BUFB : 0;
#pragma unroll
        for (int ks = 0; ks < 2; ks++) {
            uint32_t af[4][4], bf[4][4];
#pragma unroll
            for (int mi = 0; mi < 4; mi++)
                ldsm4(af[mi], a_addr0 + aoff + ((mi * 16 * 20 + ks * 8) << 2));
#pragma unroll
            for (int nj = 0; nj < 4; nj++)
                ldsm4(bf[nj], b_addr0 + aoff + ((nj * 16 * 20 + ks * 8) << 2));
#pragma unroll
            for (int mi = 0; mi < 4; mi++)
#pragma unroll
                for (int ni = 0; ni < 8; ni++)
                    mma8(acc[mi][ni], af[mi], &bf[ni >> 1][(ni & 1) * 2]);
        }
        __syncthreads();
    }

#pragma unroll
    for (int mi = 0; mi < 4; mi++)
#pragma unroll
        for (int ni = 0; ni < 8; ni++) {
            int row = m0 + wm * 64 + mi * 16 + r;
            int col = n0 + wn * 64 + ni * 8 + 2 * c;
#pragma unroll
            for (int hrow = 0; hrow < 2; hrow++) {
                float v0 = acc[mi][ni][hrow * 2 + 0];
                float v1 = acc[mi][ni][hrow * 2 + 1];
                __nv_bfloat16 h0, l0, h1, l1;
                split2(v0, h0, l0);
                split2(v1, h1, l1);
                size_t idx = (size_t)(row + 8 * hrow) * N + col;
                __nv_bfloat162 hh; hh.x = h0; hh.y = h1;
                __nv_bfloat162 ll; ll.x = l0; ll.y = l1;
                *(__nv_bfloat162*)&Chi[idx] = hh;
                *(__nv_bfloat162*)&Clo[idx] = ll;
            }
        }
}

// ---------------------------------------------------------------------------
// bf16 hi/lo split-3 NT GEMM:  C[M,N] = A[M,K] @ B[N,K]^T at ~fp32 accuracy.
// D += Ah*Bh + Al*Bh + Ah*Bl  (3x m16n8k16 bf16, ll term dropped ~2^-18).
// 128 threads, warp tile 64x64 (2x2), CTA 128x128, BK=16, cp.async 2-stage.
// smem: per buffer Ahi[128][12] Alo Bhi Blo words (stride 12: conflict-free
// LDSM phases, 16B chunks at +0/+4). 2 x 6144 words = 49,152 B dynamic.
// CVTC: round C to tf32 (for flash consumers).
// ---------------------------------------------------------------------------
struct B3Batch {
    const __nv_bfloat16 *Ah[3], *Al[3], *Bh[3], *Bl[3];
    float* C[3];
};

#define B3_STG_W 6144
#define B3_AHI 0
#define B3_ALO 1536
#define B3_BHI 3072
#define B3_BLO 4608
#define B3_SMEM_BYTES (2 * B3_STG_W * 4)

template<bool CVTC>
__global__ __launch_bounds__(128) void gemm_b3(B3Batch gb, int M, int N, int K)
{
    extern __shared__ uint32_t sm[];
    const int bz = blockIdx.z;
    const __nv_bfloat16* __restrict__ Ah = gb.Ah[bz];
    const __nv_bfloat16* __restrict__ Al = gb.Al[bz];
    const __nv_bfloat16* __restrict__ Bh = gb.Bh[bz];
    const __nv_bfloat16* __restrict__ Bl = gb.Bl[bz];
    float* __restrict__ C = gb.C[bz];

    const int tid  = threadIdx.x;
    const int lane = tid & 31, wid = tid >> 5;
    const int wm = wid & 1, wn = wid >> 1;
    const int m0 = blockIdx.y * 128, n0 = blockIdx.x * 128;
    const int r = lane >> 2, c = lane & 3;

    const int l15   = lane & 15;
    const int khalf = (lane >> 4) & 1;            // A: k-half select
    const int b_r   = (lane & 7) + ((lane & 16) >> 1);
    const int b_kh  = (lane >> 3) & 1;            // B: k-half select

    const uint32_t base = smem_u32(sm);
    const uint32_t a_hi0 = base + ((B3_AHI + (wm * 64 + l15) * 12 + khalf * 4) << 2);
    const uint32_t a_lo0 = base + ((B3_ALO + (wm * 64 + l15) * 12 + khalf * 4) << 2);
    const uint32_t b_hi0 = base + ((B3_BHI + (wn * 64 + b_r) * 12 + b_kh * 4) << 2);
    const uint32_t b_lo0 = base + ((B3_BLO + (wn * 64 + b_r) * 12 + b_kh * 4) << 2);

    // loaders: thread owns row tid of each region; 2 x 16B chunks per row
    const __nv_bfloat16* gAh = Ah + (size_t)(m0 + tid) * K;
    const __nv_bfloat16* gAl = Al + (size_t)(m0 + tid) * K;
    const __nv_bfloat16* gBh = Bh + (size_t)(n0 + tid) * K;
    const __nv_bfloat16* gBl = Bl + (size_t)(n0 + tid) * K;

    auto issue = [&](int kt, int buf) {
        const uint32_t so = base + (uint32_t)buf * (B3_STG_W * 4);
        const int k0 = kt * 16;
#pragma unroll
        for (int i = 0; i < 2; i++) {
            const uint32_t roff = ((tid * 12 + i * 4) << 2);
            cp_async16(so + (B3_AHI << 2) + roff, gAh + k0 + i * 8);
            cp_async16(so + (B3_ALO << 2) + roff, gAl + k0 + i * 8);
            cp_async16(so + (B3_BHI << 2) + roff, gBh + k0 + i * 8);
            cp_async16(so + (B3_BLO << 2) + roff, gBl + k0 + i * 8);
        }
        cp_commit();
    };

    float acc[4][8][4] = {};
    const int ntiles = K / 16;
    issue(0, 0);
    issue(1, 1);

    for (int kt = 0; kt < ntiles; kt++) {
        const int buf = kt & 1;
        asm volatile("cp.async.wait_group 1;" ::: "memory");
        __syncthreads();

        const uint32_t so = (uint32_t)buf * (B3_STG_W * 4);
        uint32_t ah[4][4], al[4][4], bh[4][4], bl[4][4];
#pragma unroll
        for (int mi = 0; mi < 4; mi++) {
            ldsm4(ah[mi], a_hi0 + so + ((mi * 16 * 12) << 2));
            ldsm4(al[mi], a_lo0 + so + ((mi * 16 * 12) << 2));
        }
#pragma unroll
        for (int nj = 0; nj < 4; nj++) {
            ldsm4(bh[nj], b_hi0 + so + ((nj * 16 * 12) << 2));
            ldsm4(bl[nj], b_lo0 + so + ((nj * 16 * 12) << 2));
        }
#pragma unroll
        for (int mi = 0; mi < 4; mi++)
#pragma unroll
            for (int ni = 0; ni < 8; ni++) {
                const uint32_t* bhp = &bh[ni >> 1][(ni & 1) * 2];
                const uint32_t* blp = &bl[ni >> 1][(ni & 1) * 2];
                mma16(acc[mi][ni], ah[mi], bhp);
                mma16(acc[mi][ni], al[mi], bhp);
                mma16(acc[mi][ni], ah[mi], blp);
            }

        __syncthreads();
        if (kt + 2 < ntiles) issue(kt + 2, buf);
        else cp_commit();
    }

#pragma unroll
    for (int mi = 0; mi < 4; mi++)
#pragma unroll
        for (int ni = 0; ni < 8; ni++) {
            int row = m0 + wm * 64 + mi * 16 + r;
            int col = n0 + wn * 64 + ni * 8 + 2 * c;
            float v0 = acc[mi][ni][0], v1 = acc[mi][ni][1];
            float v2 = acc[mi][ni][2], v3 = acc[mi][ni][3];
            if (CVTC) {
                v0 = __uint_as_float(f2tf(v0)); v1 = __uint_as_float(f2tf(v1));
                v2 = __uint_as_float(f2tf(v2)); v3 = __uint_as_float(f2tf(v3));
            }
            *(float2*)&C[(size_t)row * N + col]       = make_float2(v0, v1);
            *(float2*)&C[(size_t)(row + 8) * N + col] = make_float2(v2, v3);
        }
}

// ---------------------------------------------------------------------------
// Flash attention (tf32 mma.sync), key tile 64, exp2 softmax — R12-proven,
// epilogue now writes bf16 hi/lo split of O for the output b3 GEMM.
// ---------------------------------------------------------------------------
#define KS_OFF 0
#define VS_OFF (2*64*68)
#define PS_OFF (VS_OFF + 2*64*72)
#define FLASH_SMEM_BYTES ((PS_OFF + 4*32*68) * 4)

__global__ __launch_bounds__(128, 2) void flash_tc()
{
    extern __shared__ uint32_t dsm[];
    uint32_t* Ks = dsm + KS_OFF;
    uint32_t* Vs = dsm + VS_OFF;
    uint32_t* Ps = dsm + PS_OFF;

    const int tid  = threadIdx.x;
    const int lane = tid & 31, w = tid >> 5;
    const int r = lane >> 2, c = lane & 3;
    const int s0 = blockIdx.x * 128;
    const int bh = blockIdx.y;
    const int h = bh & (HH - 1), b = bh / HH;

    const int l15   = lane & 15;
    const int khalf = (lane >> 4) & 1;
    const int b_r   = (lane & 7) + ((lane & 16) >> 1);
    const int b_k4  = (lane & 8) >> 1;

    const uint32_t KBUF = 64 * 68 * 4;
    const uint32_t ks_base = smem_u32(Ks);
    const uint32_t vs_base = smem_u32(Vs);
    const uint32_t ks_addr = ks_base + ((b_r * 68 + b_k4) << 2);
    const uint32_t ps_addr = smem_u32(Ps + w * 32 * 68) + ((l15 * 68 + 4 * khalf) << 2);

    const float QS = 0.18033688f;   // 0.125 * log2(e)
    uint32_t qa[2][8][4];
#pragma unroll
    for (int mi = 0; mi < 2; mi++) {
        const size_t qb = (size_t)(b * SS + s0 + w * 32 + mi * 16) * DD + h * EHD;
#pragma unroll
        for (int kt = 0; kt < 8; kt++) {
            qa[mi][kt][0] = f2tf(QS * g_q[qb + (size_t)r       * DD + kt * 8 + c]);
            qa[mi][kt][1] = f2tf(QS * g_q[qb + (size_t)(r + 8) * DD + kt * 8 + c]);
            qa[mi][kt][2] = f2tf(QS * g_q[qb + (size_t)r       * DD + kt * 8 + c + 4]);
            qa[mi][kt][3] = f2tf(QS * g_q[qb + (size_t)(r + 8) * DD + kt * 8 + c + 4]);
        }
    }

    const int trow = tid >> 4;
    const int tc4  = (tid & 15) * 4;
    auto cp_kv = [&](int t0, int buf) {
#pragma unroll
        for (int i = 0; i < 8; i++) {
            const int row = trow + i * 8;
            const size_t g = (size_t)(b * SS + t0 + row) * DD + h * EHD + tc4;
            cp_async16(ks_base + ((buf * 64 * 68 + row * 68 + tc4) << 2), &g_k[g]);
            cp_async16(vs_base + ((buf * 64 * 72 + row * 72 + tc4) << 2), &g_v[g]);
        }
        cp_commit();
    };

    float o[2][8][4] = {};
    float mv[2][2], lv[2][2];
#pragma unroll
    for (int mi = 0; mi < 2; mi++) { mv[mi][0] = mv[mi][1] = -1e30f; lv[mi][0] = lv[mi][1] = 0.f; }

    const int NT = SS / 64;
    cp_kv(0, 0);
    cp_kv(64, 1);

    for (int ti = 0; ti < NT; ti++) {
        const int buf = ti & 1;
        asm volatile("cp.async.wait_group 1;" ::: "memory");
        __syncthreads();

        const uint32_t koff = buf ? KBUF : 0;

        float sc[2][8][4] = {};
#pragma unroll
        for (int kst = 0; kst < 8; kst++) {
            uint32_t kb[4][4];
#pragma unroll
            for (int j = 0; j < 4; j++)
                ldsm4(kb[j], ks_addr + koff + ((j * 16 * 68 + kst * 8) << 2));
#pragma unroll
            for (int nt = 0; nt < 8; nt++) {
                mma8(sc[0][nt], qa[0][kst], &kb[nt >> 1][(nt & 1) * 2]);
                mma8(sc[1][nt], qa[1][kst], &kb[nt >> 1][(nt & 1) * 2]);
            }
        }

        bool need_rescale = false;
        float cor[2][2];
#pragma unroll
        for (int mi = 0; mi < 2; mi++) {
            float t0m = -1e30f, t1m = -1e30f;
#pragma unroll
            for (int nt = 0; nt < 8; nt++) {
                t0m = fmaxf(t0m, fmaxf(sc[mi][nt][0], sc[mi][nt][1]));
                t1m = fmaxf(t1m, fmaxf(sc[mi][nt][2], sc[mi][nt][3]));
            }
            t0m = fmaxf(t0m, __shfl_xor_sync(0xffffffff, t0m, 1));
            t0m = fmaxf(t0m, __shfl_xor_sync(0xffffffff, t0m, 2));
            t1m = fmaxf(t1m, __shfl_xor_sync(0xffffffff, t1m, 1));
            t1m = fmaxf(t1m, __shfl_xor_sync(0xffffffff, t1m, 2));

            float mn0 = fmaxf(mv[mi][0], t0m), mn1 = fmaxf(mv[mi][1], t1m);
            cor[mi][0] = ex2(mv[mi][0] - mn0);
            cor[mi][1] = ex2(mv[mi][1] - mn1);
            need_rescale |= (mn0 > mv[mi][0]) || (mn1 > mv[mi][1]);
            mv[mi][0] = mn0; mv[mi][1] = mn1;

            uint32_t* Pw = Ps + w * 32 * 68;
            float ps0 = 0.f, ps1 = 0.f;
#pragma unroll
            for (int nt = 0; nt < 8; nt++) {
                float p0 = ex2(sc[mi][nt][0] - mn0);
                float p1 = ex2(sc[mi][nt][1] - mn0);
                float p2 = ex2(sc[mi][nt][2] - mn1);
                float p3 = ex2(sc[mi][nt][3] - mn1);
                ps0 += p0 + p1; ps1 += p2 + p3;
                Pw[(mi * 16 + r    ) * 68 + nt * 8 + 2 * c    ] = f2tf(p0);
                Pw[(mi * 16 + r    ) * 68 + nt * 8 + 2 * c + 1] = f2tf(p1);
                Pw[(mi * 16 + r + 8) * 68 + nt * 8 + 2 * c    ] = f2tf(p2);
                Pw[(mi * 16 + r + 8) * 68 + nt * 8 + 2 * c + 1] = f2tf(p3);
            }
            ps0 += __shfl_xor_sync(0xffffffff, ps0, 1);
            ps0 += __shfl_xor_sync(0xffffffff, ps0, 2);
            ps1 += __shfl_xor_sync(0xffffffff, ps1, 1);
            ps1 += __shfl_xor_sync(0xffffffff, ps1, 2);
            lv[mi][0] = lv[mi][0] * cor[mi][0] + ps0;
            lv[mi][1] = lv[mi][1] * cor[mi][1] + ps1;
        }

        if (__ballot_sync(0xffffffff, need_rescale)) {
#pragma unroll
            for (int mi = 0; mi < 2; mi++)
#pragma unroll
                for (int ne = 0; ne < 8; ne++) {
                    o[mi][ne][0] *= cor[mi][0]; o[mi][ne][1] *= cor[mi][0];
                    o[mi][ne][2] *= cor[mi][1]; o[mi][ne][3] *= cor[mi][1];
                }
        }

        __syncwarp();

        const uint32_t* Vb = Vs + (size_t)buf * 64 * 72;
#pragma unroll
        for (int k2 = 0; k2 < 8; k2++) {
            uint32_t pa0[4], pa1[4];
            ldsm4(pa0, ps_addr + ((k2 * 8) << 2));
            ldsm4(pa1, ps_addr + ((16 * 68 + k2 * 8) << 2));
#pragma unroll
            for (int ne = 0; ne < 8; ne++) {
                uint32_t bf2[2];
                bf2[0] = Vb[(k2 * 8 + c    ) * 72 + ne * 8 + r];
                bf2[1] = Vb[(k2 * 8 + c + 4) * 72 + ne * 8 + r];
                mma8(o[0][ne], pa0, bf2);
                mma8(o[1][ne], pa1, bf2);
            }
        }

        __syncthreads();
        if (ti + 2 < NT) cp_kv((ti + 2) * 64, buf);
    }

    // epilogue: write O as bf16 hi/lo split (consumed by output b3 GEMM)
#pragma unroll
    for (int mi = 0; mi < 2; mi++) {
        const float inv0 = 1.f / lv[mi][0], inv1 = 1.f / lv[mi][1];
        const size_t ob = (size_t)(b * SS + s0 + w * 32 + mi * 16) * DD + h * EHD;
#pragma unroll
        for (int ne = 0; ne < 8; ne++) {
            const int col = ne * 8 + 2 * c;
            {
                float a0 = o[mi][ne][0] * inv0, a1 = o[mi][ne][1] * inv0;
                __nv_bfloat16 h0, l0, h1, l1;
                split2(a0, h0, l0); split2(a1, h1, l1);
                __nv_bfloat162 hh; hh.x = h0; hh.y = h1;
                __nv_bfloat162 ll; ll.x = l0; ll.y = l1;
                *(__nv_bfloat162*)&g_o_hi[ob + (size_t)r * DD + col] = hh;
                *(__nv_bfloat162*)&g_o_lo[ob + (size_t)r * DD + col] = ll;
            }
            {
                float a2 = o[mi][ne][2] * inv1, a3 = o[mi][ne][3] * inv1;
                __nv_bfloat16 h2, l2, h3, l3;
                split2(a2, h2, l2); split2(a3, h3, l3);
                __nv_bfloat162 hh; hh.x = h2; hh.y = h3;
                __nv_bfloat162 ll; ll.x = l2; ll.y = l3;
                *(__nv_bfloat162*)&g_o_hi[ob + (size_t)(r + 8) * DD + col] = hh;
                *(__nv_bfloat162*)&g_o_lo[ob + (size_t)(r + 8) * DD + col] = ll;
            }
        }
    }
}

// ---------------------------------------------------------------------------
extern "C" void kernel_launch(void* const* d_in, const int* in_sizes, int n_in,
                              void* d_out, int out_size)
{
    (void)in_sizes; (void)n_in; (void)out_size;
    const float* E  = (const float*)d_in[0];
    const float* WQ = (const float*)d_in[1];
    const float* WK = (const float*)d_in[2];
    const float* WV = (const float*)d_in[3];
    const float* WO = (const float*)d_in[4];
    const float* HQ = (const float*)d_in[5];
    const float* HK = (const float*)d_in[6];
    const float* HV = (const float*)d_in[7];
    float* out = (float*)d_out;

    float *q, *k, *v;
    __nv_bfloat16 *e_hi, *e_lo, *o_hi, *o_lo, *w_hi, *w_lo, *wo_hi, *wo_lo;
    cudaGetSymbolAddress((void**)&q,     g_q);
    cudaGetSymbolAddress((void**)&k,     g_k);
    cudaGetSymbolAddress((void**)&v,     g_v);
    cudaGetSymbolAddress((void**)&e_hi,  g_e_hi);
    cudaGetSymbolAddress((void**)&e_lo,  g_e_lo);
    cudaGetSymbolAddress((void**)&o_hi,  g_o_hi);
    cudaGetSymbolAddress((void**)&o_lo,  g_o_lo);
    cudaGetSymbolAddress((void**)&w_hi,  g_w_hi);
    cudaGetSymbolAddress((void**)&w_lo,  g_w_lo);
    cudaGetSymbolAddress((void**)&wo_hi, g_wo_hi);
    cudaGetSymbolAddress((void**)&wo_lo, g_wo_lo);

    cudaFuncSetAttribute(flash_tc, cudaFuncAttributeMaxDynamicSharedMemorySize,
                         FLASH_SMEM_BYTES);
    cudaFuncSetAttribute(gemm_b3<true>,
                         cudaFuncAttributeMaxDynamicSharedMemorySize, B3_SMEM_BYTES);
    cudaFuncSetAttribute(gemm_b3<false>,
                         cudaFuncAttributeMaxDynamicSharedMemorySize, B3_SMEM_BYTES);

    // 0) split E and WO into bf16 hi/lo
    split_bf16<<<(MM*DD + 255)/256, 256>>>(E,  e_hi,  e_lo,  MM*DD);
    split_bf16<<<(DD*DD + 255)/256, 256>>>(WO, wo_hi, wo_lo, DD*DD);

    // 1) Weff = HXcat @ WX (NN tf32), epilogue -> bf16 hi/lo
    WBatch gw;
    gw.A[0] = HQ; gw.B[0] = WQ;
    gw.A[1] = HK; gw.B[1] = WK;
    gw.A[2] = HV; gw.B[2] = WV;
    gemm_nn_w<<<dim3(DD/128, DD/128, 3), 128>>>(gw, DD, DD, DD);

    // 2) q/k/v = E @ Weff^T  (bf16 split-3), C tf32-rounded fp32
    B3Batch ga;
    for (int i = 0; i < 3; i++) {
        ga.Ah[i] = e_hi; ga.Al[i] = e_lo;
        ga.Bh[i] = w_hi + (size_t)i * DD * DD;
        ga.Bl[i] = w_lo + (size_t)i * DD * DD;
    }
    ga.C[0] = q; ga.C[1] = k; ga.C[2] = v;
    gemm_b3<true><<<dim3(DD/128, MM/128, 3), 128, B3_SMEM_BYTES>>>(ga, MM, DD, DD);

    // 3) attention (writes bf16 hi/lo split O)
    flash_tc<<<dim3(SS/128, BB*HH), 128, FLASH_SMEM_BYTES>>>();

    // 4) out = O @ WO^T  (bf16 split-3), C fp32
    B3Batch go;
    for (int i = 0; i < 3; i++) {
        go.Ah[i] = o_hi; go.Al[i] = o_lo;
        go.Bh[i] = wo_hi; go.Bl[i] = wo_lo;
        go.C[i] = out;
    }
    gemm_b3<false><<<dim3(DD/128, MM/128, 1), 128, B3_SMEM_BYTES>>>(go, MM, DD, DD);
}

// round 14
// speedup vs baseline: 1.0006x; 1.0006x over previous
#include <cuda_runtime.h>
#include <cuda_bf16.h>
#include <cstdint>

#define BB 2
#define SS 2048
#define DD 1024
#define HH 16
#define EHD 64
#define MM (BB*SS)   // 4096

// fp32 activations (tf32-rounded) for flash
__device__ float g_q[MM*DD];
__device__ float g_k[MM*DD];
__device__ float g_v[MM*DD];
// bf16 hi/lo split operands for the b3 GEMMs
__device__ __nv_bfloat16 g_e_hi[MM*DD],  g_e_lo[MM*DD];
__device__ __nv_bfloat16 g_o_hi[MM*DD],  g_o_lo[MM*DD];
__device__ __nv_bfloat16 g_w_hi[3*DD*DD], g_w_lo[3*DD*DD];   // Weff q,k,v
__device__ __nv_bfloat16 g_wo_hi[DD*DD],  g_wo_lo[DD*DD];

__device__ __forceinline__ uint32_t f2tf(float x) {
    uint32_t u; asm("cvt.rna.tf32.f32 %0, %1;" : "=r"(u) : "f"(x)); return u;
}

template<bool DOCVT>
__device__ __forceinline__ uint4 pack4(float4 v) {
    if (DOCVT)
        return make_uint4(f2tf(v.x), f2tf(v.y), f2tf(v.z), f2tf(v.w));
    return make_uint4(__float_as_uint(v.x), __float_as_uint(v.y),
                      __float_as_uint(v.z), __float_as_uint(v.w));
}

__device__ __forceinline__ uint32_t smem_u32(const void* p) {
    uint32_t a;
    asm("{ .reg .u64 t; cvta.to.shared.u64 t, %1; cvt.u32.u64 %0, t; }"
        : "=r"(a) : "l"(p));
    return a;
}

__device__ __forceinline__ void ldsm4(uint32_t* d, uint32_t addr) {
    asm volatile("ldmatrix.sync.aligned.m8n8.x4.shared.b16 {%0,%1,%2,%3}, [%4];"
        : "=r"(d[0]), "=r"(d[1]), "=r"(d[2]), "=r"(d[3]) : "r"(addr));
}

// tf32 m16n8k8
__device__ __forceinline__ void mma8(float* d, const uint32_t* a, const uint32_t* b) {
    asm volatile("mma.sync.aligned.m16n8k8.row.col.f32.tf32.tf32.f32 "
        "{%0,%1,%2,%3}, {%4,%5,%6,%7}, {%8,%9}, {%0,%1,%2,%3};\n"
        : "+f"(d[0]), "+f"(d[1]), "+f"(d[2]), "+f"(d[3])
        : "r"(a[0]), "r"(a[1]), "r"(a[2]), "r"(a[3]), "r"(b[0]), "r"(b[1]));
}

// bf16 m16n8k16
__device__ __forceinline__ void mma16(float* d, const uint32_t* a, const uint32_t* b) {
    asm volatile("mma.sync.aligned.m16n8k16.row.col.f32.bf16.bf16.f32 "
        "{%0,%1,%2,%3}, {%4,%5,%6,%7}, {%8,%9}, {%0,%1,%2,%3};\n"
        : "+f"(d[0]), "+f"(d[1]), "+f"(d[2]), "+f"(d[3])
        : "r"(a[0]), "r"(a[1]), "r"(a[2]), "r"(a[3]), "r"(b[0]), "r"(b[1]));
}

__device__ __forceinline__ void cp_async16(uint32_t saddr, const void* gaddr) {
    asm volatile("cp.async.ca.shared.global [%0], [%1], 16;"
                 :: "r"(saddr), "l"(gaddr) : "memory");
}
__device__ __forceinline__ void cp_commit() {
    asm volatile("cp.async.commit_group;" ::: "memory");
}

__device__ __forceinline__ float ex2(float x) {
    float r; asm("ex2.approx.f32 %0, %1;" : "=f"(r) : "f"(x)); return r;
}

__device__ __forceinline__ void split2(float x, __nv_bfloat16& h, __nv_bfloat16& l) {
    h = __float2bfloat16_rn(x);
    l = __float2bfloat16_rn(x - __bfloat162float(h));
}

// ---------------------------------------------------------------------------
// Elementwise bf16 hi/lo split producer
// ---------------------------------------------------------------------------
__global__ void split_bf16(const float* __restrict__ s,
                           __nv_bfloat16* __restrict__ hi,
                           __nv_bfloat16* __restrict__ lo, int n)
{
    int i = blockIdx.x * blockDim.x + threadIdx.x;
    if (i < n) {
        __nv_bfloat16 h, l;
        split2(s[i], h, l);
        hi[i] = h; lo[i] = l;
    }
}

// ---------------------------------------------------------------------------
// Weight-prep GEMM (NN, tf32 internals, R12-proven shape):
// Weff = HXcat[1024,1024] @ WX[1024,1024]; epilogue writes bf16 hi/lo split.
// 128 threads, warp tile 64x64 (2x2), CTA tile 128x128, BK=16, 2-stage buffer.
// ---------------------------------------------------------------------------
struct WBatch { const float* A[3]; const float* B[3]; };

__global__ __launch_bounds__(128) void gemm_nn_w(WBatch gb, int M, int N, int K)
{
    __shared__ uint32_t As[2][128][20];
    __shared__ uint32_t Bs[2][128][20];
    const float* __restrict__ A  = gb.A[blockIdx.z];
    const float* __restrict__ Bm = gb.B[blockIdx.z];
    __nv_bfloat16* __restrict__ Chi = g_w_hi + (size_t)blockIdx.z * DD * DD;
    __nv_bfloat16* __restrict__ Clo = g_w_lo + (size_t)blockIdx.z * DD * DD;

    const int tid  = threadIdx.x;
    const int lane = tid & 31, wid = tid >> 5;
    const int wm = wid & 1, wn = wid >> 1;
    const int m0 = blockIdx.y * 128, n0 = blockIdx.x * 128;
    const int r = lane >> 2, c = lane & 3;

    const int l15   = lane & 15;
    const int khalf = (lane >> 4) & 1;
    const int b_r   = (lane & 7) + ((lane & 16) >> 1);
    const int b_k4  = (lane & 8) >> 1;

    const uint32_t As_base = smem_u32(&As[0][0][0]);
    const uint32_t Bs_base = smem_u32(&Bs[0][0][0]);
    const uint32_t BUFB = 128 * 20 * 4;
    const uint32_t a_addr0 = As_base + (((wm * 64 + l15) * 20 + 4 * khalf) << 2);
    const uint32_t b_addr0 = Bs_base + (((wn * 64 + b_r) * 20 + b_k4) << 2);

    const int arow = tid >> 2, akq = (tid & 3) * 4;
    const int bkk  = tid & 15, bc4 = tid >> 4;

    float acc[4][8][4] = {};
    float4 pa[4], pb[4];

    auto ldg_tile = [&](int k0) {
#pragma unroll
        for (int i = 0; i < 4; i++)
            pa[i] = *(const float4*)&A[(size_t)(m0 + arow + 32 * i) * K + k0 + akq];
#pragma unroll
        for (int i = 0; i < 4; i++)
            pb[i] = *(const float4*)&Bm[(size_t)(k0 + bkk) * N + n0 + (bc4 + 8 * i) * 4];
    };
    auto sts_tile = [&](int buf) {
#pragma unroll
        for (int i = 0; i < 4; i++)
            *(uint4*)&As[buf][arow + 32 * i][akq] = pack4<true>(pa[i]);
#pragma unroll
        for (int i = 0; i < 4; i++) {
            uint4 u = pack4<true>(pb[i]);
            Bs[buf][(bc4 + 8 * i) * 4 + 0][bkk] = u.x;
            Bs[buf][(bc4 + 8 * i) * 4 + 1][bkk] = u.y;
            Bs[buf][(bc4 + 8 * i) * 4 + 2][bkk] = u.z;
            Bs[buf][(bc4 + 8 * i) * 4 + 3][bkk] = u.w;
        }
    };

    const int ntiles = K / 16;
    ldg_tile(0);
    sts_tile(0);
    if (ntiles > 1) ldg_tile(16);
    __syncthreads();

    for (int kt = 0; kt < ntiles; kt++) {
        const int buf = kt & 1;
        if (kt + 1 < ntiles) {
            sts_tile(buf ^ 1);
            if (kt + 2 < ntiles) ldg_tile((kt + 2) * 16);
        }

        const uint32_t aoff = buf ? BUFB : 0;
#pragma unroll
        for (int ks = 0; ks < 2; ks++) {
            uint32_t af[4][4], bf[4][4];
#pragma unroll
            for (int mi = 0; mi < 4; mi++)
                ldsm4(af[mi], a_addr0 + aoff + ((mi * 16 * 20 + ks * 8) << 2));
#pragma unroll
            for (int nj = 0; nj < 4; nj++)
                ldsm4(bf[nj], b_addr0 + aoff + ((nj * 16 * 20 + ks * 8) << 2));
#pragma unroll
            for (int mi = 0; mi < 4; mi++)
#pragma unroll
                for (int ni = 0; ni < 8; ni++)
                    mma8(acc[mi][ni], af[mi], &bf[ni >> 1][(ni & 1) * 2]);
        }
        __syncthreads();
    }

#pragma unroll
    for (int mi = 0; mi < 4; mi++)
#pragma unroll
        for (int ni = 0; ni < 8; ni++) {
            int row = m0 + wm * 64 + mi * 16 + r;
            int col = n0 + wn * 64 + ni * 8 + 2 * c;
#pragma unroll
            for (int hrow = 0; hrow < 2; hrow++) {
                float v0 = acc[mi][ni][hrow * 2 + 0];
                float v1 = acc[mi][ni][hrow * 2 + 1];
                __nv_bfloat16 h0, l0, h1, l1;
                split2(v0, h0, l0);
                split2(v1, h1, l1);
                size_t idx = (size_t)(row + 8 * hrow) * N + col;
                __nv_bfloat162 hh; hh.x = h0; hh.y = h1;
                __nv_bfloat162 ll; ll.x = l0; ll.y = l1;
                *(__nv_bfloat162*)&Chi[idx] = hh;
                *(__nv_bfloat162*)&Clo[idx] = ll;
            }
        }
}

// ---------------------------------------------------------------------------
// bf16 hi/lo split-3 NT GEMM:  C[M,N] = A[M,K] @ B[N,K]^T at ~fp32 accuracy.
// D += Ah*Bh + Al*Bh + Ah*Bl  (3x m16n8k16 bf16, ll term dropped ~2^-18).
// 128 threads, warp tile 64x64 (2x2), CTA 128x128, BK=16, cp.async 2-stage.
// smem: per buffer Ahi[128][12] Alo Bhi Blo words (stride 12: conflict-free
// LDSM phases, 16B chunks at +0/+4). 2 x 6144 words = 49,152 B dynamic.
// CVTC: round C to tf32 (for flash consumers).
// ---------------------------------------------------------------------------
struct B3Batch {
    const __nv_bfloat16 *Ah[3], *Al[3], *Bh[3], *Bl[3];
    float* C[3];
};

#define B3_STG_W 6144
#define B3_AHI 0
#define B3_ALO 1536
#define B3_BHI 3072
#define B3_BLO 4608
#define B3_SMEM_BYTES (2 * B3_STG_W * 4)

template<bool CVTC>
__global__ __launch_bounds__(128) void gemm_b3(B3Batch gb, int M, int N, int K)
{
    extern __shared__ uint32_t sm[];
    const int bz = blockIdx.z;
    const __nv_bfloat16* __restrict__ Ah = gb.Ah[bz];
    const __nv_bfloat16* __restrict__ Al = gb.Al[bz];
    const __nv_bfloat16* __restrict__ Bh = gb.Bh[bz];
    const __nv_bfloat16* __restrict__ Bl = gb.Bl[bz];
    float* __restrict__ C = gb.C[bz];

    const int tid  = threadIdx.x;
    const int lane = tid & 31, wid = tid >> 5;
    const int wm = wid & 1, wn = wid >> 1;
    const int m0 = blockIdx.y * 128, n0 = blockIdx.x * 128;
    const int r = lane >> 2, c = lane & 3;

    const int l15   = lane & 15;
    const int khalf = (lane >> 4) & 1;            // A: k-half select
    const int b_r   = (lane & 7) + ((lane & 16) >> 1);
    const int b_kh  = (lane >> 3) & 1;            // B: k-half select

    const uint32_t base = smem_u32(sm);
    const uint32_t a_hi0 = base + ((B3_AHI + (wm * 64 + l15) * 12 + khalf * 4) << 2);
    const uint32_t a_lo0 = base + ((B3_ALO + (wm * 64 + l15) * 12 + khalf * 4) << 2);
    const uint32_t b_hi0 = base + ((B3_BHI + (wn * 64 + b_r) * 12 + b_kh * 4) << 2);
    const uint32_t b_lo0 = base + ((B3_BLO + (wn * 64 + b_r) * 12 + b_kh * 4) << 2);

    // loaders: thread owns row tid of each region; 2 x 16B chunks per row
    const __nv_bfloat16* gAh = Ah + (size_t)(m0 + tid) * K;
    const __nv_bfloat16* gAl = Al + (size_t)(m0 + tid) * K;
    const __nv_bfloat16* gBh = Bh + (size_t)(n0 + tid) * K;
    const __nv_bfloat16* gBl = Bl + (size_t)(n0 + tid) * K;

    auto issue = [&](int kt, int buf) {
        const uint32_t so = base + (uint32_t)buf * (B3_STG_W * 4);
        const int k0 = kt * 16;
#pragma unroll
        for (int i = 0; i < 2; i++) {
            const uint32_t roff = ((tid * 12 + i * 4) << 2);
            cp_async16(so + (B3_AHI << 2) + roff, gAh + k0 + i * 8);
            cp_async16(so + (B3_ALO << 2) + roff, gAl + k0 + i * 8);
            cp_async16(so + (B3_BHI << 2) + roff, gBh + k0 + i * 8);
            cp_async16(so + (B3_BLO << 2) + roff, gBl + k0 + i * 8);
        }
        cp_commit();
    };

    float acc[4][8][4] = {};
    const int ntiles = K / 16;
    issue(0, 0);
    issue(1, 1);

    for (int kt = 0; kt < ntiles; kt++) {
        const int buf = kt & 1;
        asm volatile("cp.async.wait_group 1;" ::: "memory");
        __syncthreads();

        const uint32_t so = (uint32_t)buf * (B3_STG_W * 4);
        uint32_t ah[4][4], al[4][4], bh[4][4], bl[4][4];
#pragma unroll
        for (int mi = 0; mi < 4; mi++) {
            ldsm4(ah[mi], a_hi0 + so + ((mi * 16 * 12) << 2));
            ldsm4(al[mi], a_lo0 + so + ((mi * 16 * 12) << 2));
        }
#pragma unroll
        for (int nj = 0; nj < 4; nj++) {
            ldsm4(bh[nj], b_hi0 + so + ((nj * 16 * 12) << 2));
            ldsm4(bl[nj], b_lo0 + so + ((nj * 16 * 12) << 2));
        }
#pragma unroll
        for (int mi = 0; mi < 4; mi++)
#pragma unroll
            for (int ni = 0; ni < 8; ni++) {
                const uint32_t* bhp = &bh[ni >> 1][(ni & 1) * 2];
                const uint32_t* blp = &bl[ni >> 1][(ni & 1) * 2];
                mma16(acc[mi][ni], ah[mi], bhp);
                mma16(acc[mi][ni], al[mi], bhp);
                mma16(acc[mi][ni], ah[mi], blp);
            }

        __syncthreads();
        if (kt + 2 < ntiles) issue(kt + 2, buf);
        else cp_commit();
    }

#pragma unroll
    for (int mi = 0; mi < 4; mi++)
#pragma unroll
        for (int ni = 0; ni < 8; ni++) {
            int row = m0 + wm * 64 + mi * 16 + r;
            int col = n0 + wn * 64 + ni * 8 + 2 * c;
            float v0 = acc[mi][ni][0], v1 = acc[mi][ni][1];
            float v2 = acc[mi][ni][2], v3 = acc[mi][ni][3];
            if (CVTC) {
                v0 = __uint_as_float(f2tf(v0)); v1 = __uint_as_float(f2tf(v1));
                v2 = __uint_as_float(f2tf(v2)); v3 = __uint_as_float(f2tf(v3));
            }
            *(float2*)&C[(size_t)row * N + col]       = make_float2(v0, v1);
            *(float2*)&C[(size_t)(row + 8) * N + col] = make_float2(v2, v3);
        }
}

// ---------------------------------------------------------------------------
// Flash attention (tf32 mma.sync), key tile 64, exp2 softmax — R12-proven,
// epilogue now writes bf16 hi/lo split of O for the output b3 GEMM.
// ---------------------------------------------------------------------------
#define KS_OFF 0
#define VS_OFF (2*64*68)
#define PS_OFF (VS_OFF + 2*64*72)
#define FLASH_SMEM_BYTES ((PS_OFF + 4*32*68) * 4)

__global__ __launch_bounds__(128, 2) void flash_tc()
{
    extern __shared__ uint32_t dsm[];
    uint32_t* Ks = dsm + KS_OFF;
    uint32_t* Vs = dsm + VS_OFF;
    uint32_t* Ps = dsm + PS_OFF;

    const int tid  = threadIdx.x;
    const int lane = tid & 31, w = tid >> 5;
    const int r = lane >> 2, c = lane & 3;
    const int s0 = blockIdx.x * 128;
    const int bh = blockIdx.y;
    const int h = bh & (HH - 1), b = bh / HH;

    const int l15   = lane & 15;
    const int khalf = (lane >> 4) & 1;
    const int b_r   = (lane & 7) + ((lane & 16) >> 1);
    const int b_k4  = (lane & 8) >> 1;

    const uint32_t KBUF = 64 * 68 * 4;
    const uint32_t ks_base = smem_u32(Ks);
    const uint32_t vs_base = smem_u32(Vs);
    const uint32_t ks_addr = ks_base + ((b_r * 68 + b_k4) << 2);
    const uint32_t ps_addr = smem_u32(Ps + w * 32 * 68) + ((l15 * 68 + 4 * khalf) << 2);

    const float QS = 0.18033688f;   // 0.125 * log2(e)
    uint32_t qa[2][8][4];
#pragma unroll
    for (int mi = 0; mi < 2; mi++) {
        const size_t qb = (size_t)(b * SS + s0 + w * 32 + mi * 16) * DD + h * EHD;
#pragma unroll
        for (int kt = 0; kt < 8; kt++) {
            qa[mi][kt][0] = f2tf(QS * g_q[qb + (size_t)r       * DD + kt * 8 + c]);
            qa[mi][kt][1] = f2tf(QS * g_q[qb + (size_t)(r + 8) * DD + kt * 8 + c]);
            qa[mi][kt][2] = f2tf(QS * g_q[qb + (size_t)r       * DD + kt * 8 + c + 4]);
            qa[mi][kt][3] = f2tf(QS * g_q[qb + (size_t)(r + 8) * DD + kt * 8 + c + 4]);
        }
    }

    const int trow = tid >> 4;
    const int tc4  = (tid & 15) * 4;
    auto cp_kv = [&](int t0, int buf) {
#pragma unroll
        for (int i = 0; i < 8; i++) {
            const int row = trow + i * 8;
            const size_t g = (size_t)(b * SS + t0 + row) * DD + h * EHD + tc4;
            cp_async16(ks_base + ((buf * 64 * 68 + row * 68 + tc4) << 2), &g_k[g]);
            cp_async16(vs_base + ((buf * 64 * 72 + row * 72 + tc4) << 2), &g_v[g]);
        }
        cp_commit();
    };

    float o[2][8][4] = {};
    float mv[2][2], lv[2][2];
#pragma unroll
    for (int mi = 0; mi < 2; mi++) { mv[mi][0] = mv[mi][1] = -1e30f; lv[mi][0] = lv[mi][1] = 0.f; }

    const int NT = SS / 64;
    cp_kv(0, 0);
    cp_kv(64, 1);

    for (int ti = 0; ti < NT; ti++) {
        const int buf = ti & 1;
        asm volatile("cp.async.wait_group 1;" ::: "memory");
        __syncthreads();

        const uint32_t koff = buf ? KBUF : 0;

        float sc[2][8][4] = {};
#pragma unroll
        for (int kst = 0; kst < 8; kst++) {
            uint32_t kb[4][4];
#pragma unroll
            for (int j = 0; j < 4; j++)
                ldsm4(kb[j], ks_addr + koff + ((j * 16 * 68 + kst * 8) << 2));
#pragma unroll
            for (int nt = 0; nt < 8; nt++) {
                mma8(sc[0][nt], qa[0][kst], &kb[nt >> 1][(nt & 1) * 2]);
                mma8(sc[1][nt], qa[1][kst], &kb[nt >> 1][(nt & 1) * 2]);
            }
        }

        bool need_rescale = false;
        float cor[2][2];
#pragma unroll
        for (int mi = 0; mi < 2; mi++) {
            float t0m = -1e30f, t1m = -1e30f;
#pragma unroll
            for (int nt = 0; nt < 8; nt++) {
                t0m = fmaxf(t0m, fmaxf(sc[mi][nt][0], sc[mi][nt][1]));
                t1m = fmaxf(t1m, fmaxf(sc[mi][nt][2], sc[mi][nt][3]));
            }
            t0m = fmaxf(t0m, __shfl_xor_sync(0xffffffff, t0m, 1));
            t0m = fmaxf(t0m, __shfl_xor_sync(0xffffffff, t0m, 2));
            t1m = fmaxf(t1m, __shfl_xor_sync(0xffffffff, t1m, 1));
            t1m = fmaxf(t1m, __shfl_xor_sync(0xffffffff, t1m, 2));

            float mn0 = fmaxf(mv[mi][0], t0m), mn1 = fmaxf(mv[mi][1], t1m);
            cor[mi][0] = ex2(mv[mi][0] - mn0);
            cor[mi][1] = ex2(mv[mi][1] - mn1);
            need_rescale |= (mn0 > mv[mi][0]) || (mn1 > mv[mi][1]);
            mv[mi][0] = mn0; mv[mi][1] = mn1;

            uint32_t* Pw = Ps + w * 32 * 68;
            float ps0 = 0.f, ps1 = 0.f;
#pragma unroll
            for (int nt = 0; nt < 8; nt++) {
                float p0 = ex2(sc[mi][nt][0] - mn0);
                float p1 = ex2(sc[mi][nt][1] - mn0);
                float p2 = ex2(sc[mi][nt][2] - mn1);
                float p3 = ex2(sc[mi][nt][3] - mn1);
                ps0 += p0 + p1; ps1 += p2 + p3;
                Pw[(mi * 16 + r    ) * 68 + nt * 8 + 2 * c    ] = f2tf(p0);
                Pw[(mi * 16 + r    ) * 68 + nt * 8 + 2 * c + 1] = f2tf(p1);
                Pw[(mi * 16 + r + 8) * 68 + nt * 8 + 2 * c    ] = f2tf(p2);
                Pw[(mi * 16 + r + 8) * 68 + nt * 8 + 2 * c + 1] = f2tf(p3);
            }
            ps0 += __shfl_xor_sync(0xffffffff, ps0, 1);
            ps0 += __shfl_xor_sync(0xffffffff, ps0, 2);
            ps1 += __shfl_xor_sync(0xffffffff, ps1, 1);
            ps1 += __shfl_xor_sync(0xffffffff, ps1, 2);
            lv[mi][0] = lv[mi][0] * cor[mi][0] + ps0;
            lv[mi][1] = lv[mi][1] * cor[mi][1] + ps1;
        }

        if (__ballot_sync(0xffffffff, need_rescale)) {
#pragma unroll
            for (int mi = 0; mi < 2; mi++)
#pragma unroll
                for (int ne = 0; ne < 8; ne++) {
                    o[mi][ne][0] *= cor[mi][0]; o[mi][ne][1] *= cor[mi][0];
                    o[mi][ne][2] *= cor[mi][1]; o[mi][ne][3] *= cor[mi][1];
                }
        }

        __syncwarp();

        const uint32_t* Vb = Vs + (size_t)buf * 64 * 72;
#pragma unroll
        for (int k2 = 0; k2 < 8; k2++) {
            uint32_t pa0[4], pa1[4];
            ldsm4(pa0, ps_addr + ((k2 * 8) << 2));
            ldsm4(pa1, ps_addr + ((16 * 68 + k2 * 8) << 2));
#pragma unroll
            for (int ne = 0; ne < 8; ne++) {
                uint32_t bf2[2];
                bf2[0] = Vb[(k2 * 8 + c    ) * 72 + ne * 8 + r];
                bf2[1] = Vb[(k2 * 8 + c + 4) * 72 + ne * 8 + r];
                mma8(o[0][ne], pa0, bf2);
                mma8(o[1][ne], pa1, bf2);
            }
        }

        __syncthreads();
        if (ti + 2 < NT) cp_kv((ti + 2) * 64, buf);
    }

    // epilogue: write O as bf16 hi/lo split (consumed by output b3 GEMM)
#pragma unroll
    for (int mi = 0; mi < 2; mi++) {
        const float inv0 = 1.f / lv[mi][0], inv1 = 1.f / lv[mi][1];
        const size_t ob = (size_t)(b * SS + s0 + w * 32 + mi * 16) * DD + h * EHD;
#pragma unroll
        for (int ne = 0; ne < 8; ne++) {
            const int col = ne * 8 + 2 * c;
            {
                float a0 = o[mi][ne][0] * inv0, a1 = o[mi][ne][1] * inv0;
                __nv_bfloat16 h0, l0, h1, l1;
                split2(a0, h0, l0); split2(a1, h1, l1);
                __nv_bfloat162 hh; hh.x = h0; hh.y = h1;
                __nv_bfloat162 ll; ll.x = l0; ll.y = l1;
                *(__nv_bfloat162*)&g_o_hi[ob + (size_t)r * DD + col] = hh;
                *(__nv_bfloat162*)&g_o_lo[ob + (size_t)r * DD + col] = ll;
            }
            {
                float a2 = o[mi][ne][2] * inv1, a3 = o[mi][ne][3] * inv1;
                __nv_bfloat16 h2, l2, h3, l3;
                split2(a2, h2, l2); split2(a3, h3, l3);
                __nv_bfloat162 hh; hh.x = h2; hh.y = h3;
                __nv_bfloat162 ll; ll.x = l2; ll.y = l3;
                *(__nv_bfloat162*)&g_o_hi[ob + (size_t)(r + 8) * DD + col] = hh;
                *(__nv_bfloat162*)&g_o_lo[ob + (size_t)(r + 8) * DD + col] = ll;
            }
        }
    }
}

// ---------------------------------------------------------------------------
extern "C" void kernel_launch(void* const* d_in, const int* in_sizes, int n_in,
                              void* d_out, int out_size)
{
    (void)in_sizes; (void)n_in; (void)out_size;
    const float* E  = (const float*)d_in[0];
    const float* WQ = (const float*)d_in[1];
    const float* WK = (const float*)d_in[2];
    const float* WV = (const float*)d_in[3];
    const float* WO = (const float*)d_in[4];
    const float* HQ = (const float*)d_in[5];
    const float* HK = (const float*)d_in[6];
    const float* HV = (const float*)d_in[7];
    float* out = (float*)d_out;

    float *q, *k, *v;
    __nv_bfloat16 *e_hi, *e_lo, *o_hi, *o_lo, *w_hi, *w_lo, *wo_hi, *wo_lo;
    cudaGetSymbolAddress((void**)&q,     g_q);
    cudaGetSymbolAddress((void**)&k,     g_k);
    cudaGetSymbolAddress((void**)&v,     g_v);
    cudaGetSymbolAddress((void**)&e_hi,  g_e_hi);
    cudaGetSymbolAddress((void**)&e_lo,  g_e_lo);
    cudaGetSymbolAddress((void**)&o_hi,  g_o_hi);
    cudaGetSymbolAddress((void**)&o_lo,  g_o_lo);
    cudaGetSymbolAddress((void**)&w_hi,  g_w_hi);
    cudaGetSymbolAddress((void**)&w_lo,  g_w_lo);
    cudaGetSymbolAddress((void**)&wo_hi, g_wo_hi);
    cudaGetSymbolAddress((void**)&wo_lo, g_wo_lo);

    cudaFuncSetAttribute(flash_tc, cudaFuncAttributeMaxDynamicSharedMemorySize,
                         FLASH_SMEM_BYTES);
    cudaFuncSetAttribute(gemm_b3<true>,
                         cudaFuncAttributeMaxDynamicSharedMemorySize, B3_SMEM_BYTES);
    cudaFuncSetAttribute(gemm_b3<false>,
                         cudaFuncAttributeMaxDynamicSharedMemorySize, B3_SMEM_BYTES);

    // 0) split E and WO into bf16 hi/lo
    split_bf16<<<(MM*DD + 255)/256, 256>>>(E,  e_hi,  e_lo,  MM*DD);
    split_bf16<<<(DD*DD + 255)/256, 256>>>(WO, wo_hi, wo_lo, DD*DD);

    // 1) Weff = HXcat @ WX (NN tf32), epilogue -> bf16 hi/lo
    WBatch gw;
    gw.A[0] = HQ; gw.B[0] = WQ;
    gw.A[1] = HK; gw.B[1] = WK;
    gw.A[2] = HV; gw.B[2] = WV;
    gemm_nn_w<<<dim3(DD/128, DD/128, 3), 128>>>(gw, DD, DD, DD);

    // 2) q/k/v = E @ Weff^T  (bf16 split-3), C tf32-rounded fp32
    B3Batch ga;
    for (int i = 0; i < 3; i++) {
        ga.Ah[i] = e_hi; ga.Al[i] = e_lo;
        ga.Bh[i] = w_hi + (size_t)i * DD * DD;
        ga.Bl[i] = w_lo + (size_t)i * DD * DD;
    }
    ga.C[0] = q; ga.C[1] = k; ga.C[2] = v;
    gemm_b3<true><<<dim3(DD/128, MM/128, 3), 128, B3_SMEM_BYTES>>>(ga, MM, DD, DD);

    // 3) attention (writes bf16 hi/lo split O)
    flash_tc<<<dim3(SS/128, BB*HH), 128, FLASH_SMEM_BYTES>>>();

    // 4) out = O @ WO^T  (bf16 split-3), C fp32
    B3Batch go;
    for (int i = 0; i < 3; i++) {
        go.Ah[i] = o_hi; go.Al[i] = o_lo;
        go.Bh[i] = wo_hi; go.Bl[i] = wo_lo;
        go.C[i] = out;
    }
    gemm_b3<false><<<dim3(DD/128, MM/128, 1), 128, B3_SMEM_BYTES>>>(go, MM, DD, DD);
}

// round 15
// speedup vs baseline: 1.9549x; 1.9537x over previous
#include <cuda_runtime.h>
#include <cuda_fp16.h>
#include <cstdint>

#define BB 2
#define SS 2048
#define DD 1024
#define HH 16
#define EHD 64
#define MM (BB*SS)   // 4096

// fp16 operand buffers
__device__ __half g_e_h[MM*DD];
__device__ __half g_q_h[MM*DD];
__device__ __half g_k_h[MM*DD];
__device__ __half g_v_h[MM*DD];
__device__ __half g_o_h[MM*DD];
__device__ __half g_w_h[3*DD*DD];   // Weff q,k,v (q pre-scaled by QS)
__device__ __half g_wo_h[DD*DD];

#define QS 0.18033688f   // 0.125 * log2(e)  (exp2-domain softmax scale)

__device__ __forceinline__ uint32_t f2tf(float x) {
    uint32_t u; asm("cvt.rna.tf32.f32 %0, %1;" : "=r"(u) : "f"(x)); return u;
}

__device__ __forceinline__ uint32_t smem_u32(const void* p) {
    uint32_t a;
    asm("{ .reg .u64 t; cvta.to.shared.u64 t, %1; cvt.u32.u64 %0, t; }"
        : "=r"(a) : "l"(p));
    return a;
}

__device__ __forceinline__ void ldsm4(uint32_t* d, uint32_t addr) {
    asm volatile("ldmatrix.sync.aligned.m8n8.x4.shared.b16 {%0,%1,%2,%3}, [%4];"
        : "=r"(d[0]), "=r"(d[1]), "=r"(d[2]), "=r"(d[3]) : "r"(addr));
}
__device__ __forceinline__ void ldsm4t(uint32_t* d, uint32_t addr) {
    asm volatile("ldmatrix.sync.aligned.m8n8.x4.trans.shared.b16 {%0,%1,%2,%3}, [%4];"
        : "=r"(d[0]), "=r"(d[1]), "=r"(d[2]), "=r"(d[3]) : "r"(addr));
}

// tf32 m16n8k8 (weight GEMM only)
__device__ __forceinline__ void mma8(float* d, const uint32_t* a, const uint32_t* b) {
    asm volatile("mma.sync.aligned.m16n8k8.row.col.f32.tf32.tf32.f32 "
        "{%0,%1,%2,%3}, {%4,%5,%6,%7}, {%8,%9}, {%0,%1,%2,%3};\n"
        : "+f"(d[0]), "+f"(d[1]), "+f"(d[2]), "+f"(d[3])
        : "r"(a[0]), "r"(a[1]), "r"(a[2]), "r"(a[3]), "r"(b[0]), "r"(b[1]));
}

// fp16 m16n8k16, fp32 accumulate
__device__ __forceinline__ void mma16(float* d, const uint32_t* a, const uint32_t* b) {
    asm volatile("mma.sync.aligned.m16n8k16.row.col.f32.f16.f16.f32 "
        "{%0,%1,%2,%3}, {%4,%5,%6,%7}, {%8,%9}, {%0,%1,%2,%3};\n"
        : "+f"(d[0]), "+f"(d[1]), "+f"(d[2]), "+f"(d[3])
        : "r"(a[0]), "r"(a[1]), "r"(a[2]), "r"(a[3]), "r"(b[0]), "r"(b[1]));
}

__device__ __forceinline__ void cp_async16(uint32_t saddr, const void* gaddr) {
    asm volatile("cp.async.ca.shared.global [%0], [%1], 16;"
                 :: "r"(saddr), "l"(gaddr) : "memory");
}
__device__ __forceinline__ void cp_commit() {
    asm volatile("cp.async.commit_group;" ::: "memory");
}

__device__ __forceinline__ float ex2(float x) {
    float r; asm("ex2.approx.f32 %0, %1;" : "=f"(r) : "f"(x)); return r;
}

// ---------------------------------------------------------------------------
// fp32 -> fp16 elementwise converter
// ---------------------------------------------------------------------------
__global__ void cvt_half(const float* __restrict__ s, __half* __restrict__ d, int n4)
{
    int i = blockIdx.x * blockDim.x + threadIdx.x;
    if (i < n4) {
        float4 v = ((const float4*)s)[i];
        __half2 h0 = __floats2half2_rn(v.x, v.y);
        __half2 h1 = __floats2half2_rn(v.z, v.w);
        uint2 u;
        u.x = *(uint32_t*)&h0;
        u.y = *(uint32_t*)&h1;
        ((uint2*)d)[i] = u;
    }
}

// ---------------------------------------------------------------------------
// Weight-prep GEMM (NN, tf32 internals, R12-proven):
//   Weff = HXcat[1024,1024] @ WX[1024,1024]
// epilogue writes fp16; z==0 (Q weights) additionally scaled by QS.
// 128 threads, warp tile 64x64 (2x2), CTA 128x128, BK=16, 2-stage buffer.
// ---------------------------------------------------------------------------
struct WBatch { const float* A[3]; const float* B[3]; };

__global__ __launch_bounds__(128) void gemm_nn_w(WBatch gb, int M, int N, int K)
{
    __shared__ uint32_t As[2][128][20];
    __shared__ uint32_t Bs[2][128][20];
    const float* __restrict__ A  = gb.A[blockIdx.z];
    const float* __restrict__ Bm = gb.B[blockIdx.z];
    __half* __restrict__ Ch = g_w_h + (size_t)blockIdx.z * DD * DD;
    const float csc = (blockIdx.z == 0) ? QS : 1.0f;

    const int tid  = threadIdx.x;
    const int lane = tid & 31, wid = tid >> 5;
    const int wm = wid & 1, wn = wid >> 1;
    const int m0 = blockIdx.y * 128, n0 = blockIdx.x * 128;
    const int r = lane >> 2, c = lane & 3;

    const int l15   = lane & 15;
    const int khalf = (lane >> 4) & 1;
    const int b_r   = (lane & 7) + ((lane & 16) >> 1);
    const int b_k4  = (lane & 8) >> 1;

    const uint32_t As_base = smem_u32(&As[0][0][0]);
    const uint32_t Bs_base = smem_u32(&Bs[0][0][0]);
    const uint32_t BUFB = 128 * 20 * 4;
    const uint32_t a_addr0 = As_base + (((wm * 64 + l15) * 20 + 4 * khalf) << 2);
    const uint32_t b_addr0 = Bs_base + (((wn * 64 + b_r) * 20 + b_k4) << 2);

    const int arow = tid >> 2, akq = (tid & 3) * 4;
    const int bkk  = tid & 15, bc4 = tid >> 4;

    float acc[4][8][4] = {};
    float4 pa[4], pb[4];

    auto ldg_tile = [&](int k0) {
#pragma unroll
        for (int i = 0; i < 4; i++)
            pa[i] = *(const float4*)&A[(size_t)(m0 + arow + 32 * i) * K + k0 + akq];
#pragma unroll
        for (int i = 0; i < 4; i++)
            pb[i] = *(const float4*)&Bm[(size_t)(k0 + bkk) * N + n0 + (bc4 + 8 * i) * 4];
    };
    auto sts_tile = [&](int buf) {
#pragma unroll
        for (int i = 0; i < 4; i++)
            *(uint4*)&As[buf][arow + 32 * i][akq] =
                make_uint4(f2tf(pa[i].x), f2tf(pa[i].y), f2tf(pa[i].z), f2tf(pa[i].w));
#pragma unroll
        for (int i = 0; i < 4; i++) {
            Bs[buf][(bc4 + 8 * i) * 4 + 0][bkk] = f2tf(pb[i].x);
            Bs[buf][(bc4 + 8 * i) * 4 + 1][bkk] = f2tf(pb[i].y);
            Bs[buf][(bc4 + 8 * i) * 4 + 2][bkk] = f2tf(pb[i].z);
            Bs[buf][(bc4 + 8 * i) * 4 + 3][bkk] = f2tf(pb[i].w);
        }
    };

    const int ntiles = K / 16;
    ldg_tile(0);
    sts_tile(0);
    if (ntiles > 1) ldg_tile(16);
    __syncthreads();

    for (int kt = 0; kt < ntiles; kt++) {
        const int buf = kt & 1;
        if (kt + 1 < ntiles) {
            sts_tile(buf ^ 1);
            if (kt + 2 < ntiles) ldg_tile((kt + 2) * 16);
        }

        const uint32_t aoff = buf ? BUFB : 0;
#pragma unroll
        for (int ks = 0; ks < 2; ks++) {
            uint32_t af[4][4], bf[4][4];
#pragma unroll
            for (int mi = 0; mi < 4; mi++)
                ldsm4(af[mi], a_addr0 + aoff + ((mi * 16 * 20 + ks * 8) << 2));
#pragma unroll
            for (int nj = 0; nj < 4; nj++)
                ldsm4(bf[nj], b_addr0 + aoff + ((nj * 16 * 20 + ks * 8) << 2));
#pragma unroll
            for (int mi = 0; mi < 4; mi++)
#pragma unroll
                for (int ni = 0; ni < 8; ni++)
                    mma8(acc[mi][ni], af[mi], &bf[ni >> 1][(ni & 1) * 2]);
        }
        __syncthreads();
    }

#pragma unroll
    for (int mi = 0; mi < 4; mi++)
#pragma unroll
        for (int ni = 0; ni < 8; ni++) {
            int row = m0 + wm * 64 + mi * 16 + r;
            int col = n0 + wn * 64 + ni * 8 + 2 * c;
            *(__half2*)&Ch[(size_t)row * N + col] =
                __floats2half2_rn(acc[mi][ni][0] * csc, acc[mi][ni][1] * csc);
            *(__half2*)&Ch[(size_t)(row + 8) * N + col] =
                __floats2half2_rn(acc[mi][ni][2] * csc, acc[mi][ni][3] * csc);
        }
}

// ---------------------------------------------------------------------------
// fp16 NT GEMM: C[M,N] = A[M,K] @ B[N,K]^T, fp16 operands, fp32 accum.
// 128 threads, warp tile 64x64, CTA 128x128, BK=16, 3-stage cp.async ring.
// smem: per stage A[128][24 halves] + B[128][24]; rows padded 48B (stride 12
// words: r*12 mod 32 covers all 8 bank-quads -> conflict-free b16 LDSM).
// 3 stages x 12,288 B = 36,864 B static.
// HALF_OUT: write C as fp16 (for flash/out-GEMM consumers) else fp32.
// ---------------------------------------------------------------------------
struct HBatch { const __half* A[3]; const __half* B[3]; void* C[3]; };

template<bool HALF_OUT>
__global__ __launch_bounds__(128, 2) void gemm_h(HBatch gb, int M, int N, int K)
{
    __shared__ __align__(16) __half As[3][128][24];
    __shared__ __align__(16) __half Bs[3][128][24];
    const __half* __restrict__ A  = gb.A[blockIdx.z];
    const __half* __restrict__ Bm = gb.B[blockIdx.z];

    const int tid  = threadIdx.x;
    const int lane = tid & 31, wid = tid >> 5;
    const int wm = wid & 1, wn = wid >> 1;
    const int m0 = blockIdx.y * 128, n0 = blockIdx.x * 128;
    const int r = lane >> 2, c = lane & 3;

    const int l15   = lane & 15;
    const int khalf = (lane >> 4) & 1;
    const int b_r   = (lane & 7) + ((lane & 16) >> 1);
    const int b_kh  = (lane >> 3) & 1;

    const uint32_t Ab = smem_u32(&As[0][0][0]);
    const uint32_t Bb = smem_u32(&Bs[0][0][0]);
    const uint32_t STG = 128 * 48;
    const uint32_t a0 = Ab + (wm * 64 + l15) * 48 + khalf * 16;
    const uint32_t b0 = Bb + (wn * 64 + b_r) * 48 + b_kh * 16;

    const __half* gA = A  + (size_t)(m0 + tid) * K;
    const __half* gB = Bm + (size_t)(n0 + tid) * K;
    auto issue = [&](int kt) {
        const uint32_t s = (uint32_t)(kt % 3) * STG;
        const int k0 = kt * 16;
        cp_async16(Ab + s + tid * 48,      gA + k0);
        cp_async16(Ab + s + tid * 48 + 16, gA + k0 + 8);
        cp_async16(Bb + s + tid * 48,      gB + k0);
        cp_async16(Bb + s + tid * 48 + 16, gB + k0 + 8);
        cp_commit();
    };

    float acc[4][8][4] = {};
    const int ntiles = K / 16;
    issue(0); issue(1); issue(2);

    for (int kt = 0; kt < ntiles; kt++) {
        const uint32_t s = (uint32_t)(kt % 3) * STG;
        asm volatile("cp.async.wait_group 2;" ::: "memory");
        __syncthreads();

        uint32_t af[4][4], bf[4][4];
#pragma unroll
        for (int mi = 0; mi < 4; mi++)
            ldsm4(af[mi], a0 + s + mi * 16 * 48);
#pragma unroll
        for (int nj = 0; nj < 4; nj++)
            ldsm4(bf[nj], b0 + s + nj * 16 * 48);
#pragma unroll
        for (int mi = 0; mi < 4; mi++)
#pragma unroll
            for (int ni = 0; ni < 8; ni++)
                mma16(acc[mi][ni], af[mi], &bf[ni >> 1][(ni & 1) * 2]);

        __syncthreads();
        if (kt + 3 < ntiles) issue(kt + 3);
        else cp_commit();
    }

#pragma unroll
    for (int mi = 0; mi < 4; mi++)
#pragma unroll
        for (int ni = 0; ni < 8; ni++) {
            int row = m0 + wm * 64 + mi * 16 + r;
            int col = n0 + wn * 64 + ni * 8 + 2 * c;
            if (HALF_OUT) {
                __half* Ch = (__half*)gb.C[blockIdx.z];
                *(__half2*)&Ch[(size_t)row * N + col] =
                    __floats2half2_rn(acc[mi][ni][0], acc[mi][ni][1]);
                *(__half2*)&Ch[(size_t)(row + 8) * N + col] =
                    __floats2half2_rn(acc[mi][ni][2], acc[mi][ni][3]);
            } else {
                float* Cf = (float*)gb.C[blockIdx.z];
                *(float2*)&Cf[(size_t)row * N + col] =
                    make_float2(acc[mi][ni][0], acc[mi][ni][1]);
                *(float2*)&Cf[(size_t)(row + 8) * N + col] =
                    make_float2(acc[mi][ni][2], acc[mi][ni][3]);
            }
        }
}

// ---------------------------------------------------------------------------
// fp16 flash attention: 4 warps x 32 q-rows, key tile 64, exp2 softmax.
// Q pre-scaled via Weff_q (QS). S and PV phases use m16n8k16.f16.
// V B-fragments via ldmatrix.trans (V stored [key][e]).
// smem (halves): Ks[2][64][72] @0, Vs[2][64][72] @9216, Ps[4][32][72] @18432
// rows padded to 144 B (36 words -> conflict-free LDSM). total 55,296 B.
// ---------------------------------------------------------------------------
#define F_KS 0
#define F_VS 9216
#define F_PS 18432
#define FLASH_SMEM_BYTES ((F_PS + 4*32*72) * 2)

__global__ __launch_bounds__(128, 2) void flash_h()
{
    extern __shared__ __align__(16) __half hsm[];

    const int tid  = threadIdx.x;
    const int lane = tid & 31, w = tid >> 5;
    const int r = lane >> 2, c = lane & 3;
    const int s0 = blockIdx.x * 128;
    const int bh = blockIdx.y;
    const int h = bh & (HH - 1), b = bh / HH;

    const int l15   = lane & 15;
    const int khalf = (lane >> 4) & 1;
    const int b_r   = (lane & 7) + ((lane & 16) >> 1);
    const int b_kh  = (lane >> 3) & 1;
    const int vrow  = (lane & 7) + ((lane & 8) ? 8 : 0);
    const int veoff = (lane >> 4) & 1;

    const uint32_t base = smem_u32(hsm);
    const uint32_t ksb = base;
    const uint32_t vsb = base + F_VS * 2;
    const uint32_t psb = base + F_PS * 2 + w * 32 * 144;

    const uint32_t ks_lane = ksb + b_r * 144 + b_kh * 16;
    const uint32_t ps_lane = psb + l15 * 144 + khalf * 16;
    const uint32_t vs_lane = vsb + vrow * 144 + veoff * 16;

    // Q fragments (fp16, already QS-scaled): 2 m-tiles x 4 k16-tiles
    uint32_t qa[2][4][4];
#pragma unroll
    for (int mi = 0; mi < 2; mi++) {
        const __half* qp = g_q_h + (size_t)(b * SS + s0 + w * 32 + mi * 16) * DD + h * EHD;
#pragma unroll
        for (int kt = 0; kt < 4; kt++) {
            qa[mi][kt][0] = *(const uint32_t*)&qp[(size_t)r       * DD + kt * 16 + 2 * c];
            qa[mi][kt][1] = *(const uint32_t*)&qp[(size_t)(r + 8) * DD + kt * 16 + 2 * c];
            qa[mi][kt][2] = *(const uint32_t*)&qp[(size_t)r       * DD + kt * 16 + 8 + 2 * c];
            qa[mi][kt][3] = *(const uint32_t*)&qp[(size_t)(r + 8) * DD + kt * 16 + 8 + 2 * c];
        }
    }

    // cp.async K/V loader: thread t: row t>>1, half (t&1) of the 128B row
    const int krow = tid >> 1, hf = tid & 1;
    auto cp_kv = [&](int t0, int buf) {
        const size_t g = (size_t)(b * SS + t0 + krow) * DD + h * EHD + hf * 32;
        const uint32_t d = (uint32_t)buf * 9216 + krow * 144 + hf * 64;
#pragma unroll
        for (int j = 0; j < 4; j++) {
            cp_async16(ksb + d + j * 16, g_k_h + g + j * 8);
            cp_async16(vsb + d + j * 16, g_v_h + g + j * 8);
        }
        cp_commit();
    };

    float o[2][8][4] = {};
    float mv[2][2], lv[2][2];
#pragma unroll
    for (int mi = 0; mi < 2; mi++) { mv[mi][0] = mv[mi][1] = -1e30f; lv[mi][0] = lv[mi][1] = 0.f; }

    const int NT = SS / 64;
    cp_kv(0, 0);
    cp_kv(64, 1);

    for (int ti = 0; ti < NT; ti++) {
        const int buf = ti & 1;
        asm volatile("cp.async.wait_group 1;" ::: "memory");
        __syncthreads();

        const uint32_t koff = (uint32_t)buf * 9216;

        // S = Q K^T : 32x64 per warp; 4 k16-steps x 8 n-tiles x 2 m = 64 mma16
        float sc[2][8][4] = {};
#pragma unroll
        for (int kst = 0; kst < 4; kst++) {
            uint32_t kb[4][4];
#pragma unroll
            for (int j = 0; j < 4; j++)
                ldsm4(kb[j], ks_lane + koff + j * 16 * 144 + kst * 32);
#pragma unroll
            for (int nt = 0; nt < 8; nt++) {
                mma16(sc[0][nt], qa[0][kst], &kb[nt >> 1][(nt & 1) * 2]);
                mma16(sc[1][nt], qa[1][kst], &kb[nt >> 1][(nt & 1) * 2]);
            }
        }

        // online softmax (log2 domain)
        bool need_rescale = false;
        float cor[2][2];
        __half* Pw = hsm + F_PS + w * 32 * 72;
#pragma unroll
        for (int mi = 0; mi < 2; mi++) {
            float t0m = -1e30f, t1m = -1e30f;
#pragma unroll
            for (int nt = 0; nt < 8; nt++) {
                t0m = fmaxf(t0m, fmaxf(sc[mi][nt][0], sc[mi][nt][1]));
                t1m = fmaxf(t1m, fmaxf(sc[mi][nt][2], sc[mi][nt][3]));
            }
            t0m = fmaxf(t0m, __shfl_xor_sync(0xffffffff, t0m, 1));
            t0m = fmaxf(t0m, __shfl_xor_sync(0xffffffff, t0m, 2));
            t1m = fmaxf(t1m, __shfl_xor_sync(0xffffffff, t1m, 1));
            t1m = fmaxf(t1m, __shfl_xor_sync(0xffffffff, t1m, 2));

            float mn0 = fmaxf(mv[mi][0], t0m), mn1 = fmaxf(mv[mi][1], t1m);
            cor[mi][0] = ex2(mv[mi][0] - mn0);
            cor[mi][1] = ex2(mv[mi][1] - mn1);
            need_rescale |= (mn0 > mv[mi][0]) || (mn1 > mv[mi][1]);
            mv[mi][0] = mn0; mv[mi][1] = mn1;

            float ps0 = 0.f, ps1 = 0.f;
#pragma unroll
            for (int nt = 0; nt < 8; nt++) {
                float p0 = ex2(sc[mi][nt][0] - mn0);
                float p1 = ex2(sc[mi][nt][1] - mn0);
                float p2 = ex2(sc[mi][nt][2] - mn1);
                float p3 = ex2(sc[mi][nt][3] - mn1);
                ps0 += p0 + p1; ps1 += p2 + p3;
                *(__half2*)&Pw[(mi * 16 + r    ) * 72 + nt * 8 + 2 * c] =
                    __floats2half2_rn(p0, p1);
                *(__half2*)&Pw[(mi * 16 + r + 8) * 72 + nt * 8 + 2 * c] =
                    __floats2half2_rn(p2, p3);
            }
            ps0 += __shfl_xor_sync(0xffffffff, ps0, 1);
            ps0 += __shfl_xor_sync(0xffffffff, ps0, 2);
            ps1 += __shfl_xor_sync(0xffffffff, ps1, 1);
            ps1 += __shfl_xor_sync(0xffffffff, ps1, 2);
            lv[mi][0] = lv[mi][0] * cor[mi][0] + ps0;
            lv[mi][1] = lv[mi][1] * cor[mi][1] + ps1;
        }

        if (__ballot_sync(0xffffffff, need_rescale)) {
#pragma unroll
            for (int mi = 0; mi < 2; mi++)
#pragma unroll
                for (int ne = 0; ne < 8; ne++) {
                    o[mi][ne][0] *= cor[mi][0]; o[mi][ne][1] *= cor[mi][0];
                    o[mi][ne][2] *= cor[mi][1]; o[mi][ne][3] *= cor[mi][1];
                }
        }

        __syncwarp();

        // O += P V : 4 key16-steps; P A-frags LDSM, V B-frags LDSM.trans
#pragma unroll
        for (int k2 = 0; k2 < 4; k2++) {
            uint32_t pa0[4], pa1[4];
            ldsm4(pa0, ps_lane + k2 * 32);
            ldsm4(pa1, ps_lane + 16 * 144 + k2 * 32);
            uint32_t vb[4][4];
#pragma unroll
            for (int ne = 0; ne < 4; ne++)
                ldsm4t(vb[ne], vs_lane + koff + k2 * 16 * 144 + ne * 32);
#pragma unroll
            for (int ne = 0; ne < 8; ne++) {
                mma16(o[0][ne], pa0, &vb[ne >> 1][(ne & 1) * 2]);
                mma16(o[1][ne], pa1, &vb[ne >> 1][(ne & 1) * 2]);
            }
        }

        __syncthreads();
        if (ti + 2 < NT) cp_kv((ti + 2) * 64, buf);
    }

    // epilogue: O -> fp16
#pragma unroll
    for (int mi = 0; mi < 2; mi++) {
        const float inv0 = 1.f / lv[mi][0], inv1 = 1.f / lv[mi][1];
        const size_t ob = (size_t)(b * SS + s0 + w * 32 + mi * 16) * DD + h * EHD;
#pragma unroll
        for (int ne = 0; ne < 8; ne++) {
            const int col = ne * 8 + 2 * c;
            *(__half2*)&g_o_h[ob + (size_t)r * DD + col] =
                __floats2half2_rn(o[mi][ne][0] * inv0, o[mi][ne][1] * inv0);
            *(__half2*)&g_o_h[ob + (size_t)(r + 8) * DD + col] =
                __floats2half2_rn(o[mi][ne][2] * inv1, o[mi][ne][3] * inv1);
        }
    }
}

// ---------------------------------------------------------------------------
extern "C" void kernel_launch(void* const* d_in, const int* in_sizes, int n_in,
                              void* d_out, int out_size)
{
    (void)in_sizes; (void)n_in; (void)out_size;
    const float* E  = (const float*)d_in[0];
    const float* WQ = (const float*)d_in[1];
    const float* WK = (const float*)d_in[2];
    const float* WV = (const float*)d_in[3];
    const float* WO = (const float*)d_in[4];
    const float* HQ = (const float*)d_in[5];
    const float* HK = (const float*)d_in[6];
    const float* HV = (const float*)d_in[7];
    float* out = (float*)d_out;

    __half *e_h, *q_h, *k_h, *v_h, *o_h, *w_h, *wo_h;
    cudaGetSymbolAddress((void**)&e_h,  g_e_h);
    cudaGetSymbolAddress((void**)&q_h,  g_q_h);
    cudaGetSymbolAddress((void**)&k_h,  g_k_h);
    cudaGetSymbolAddress((void**)&v_h,  g_v_h);
    cudaGetSymbolAddress((void**)&o_h,  g_o_h);
    cudaGetSymbolAddress((void**)&w_h,  g_w_h);
    cudaGetSymbolAddress((void**)&wo_h, g_wo_h);

    cudaFuncSetAttribute(flash_h, cudaFuncAttributeMaxDynamicSharedMemorySize,
                         FLASH_SMEM_BYTES);

    // 0) convert E and WO to fp16
    cvt_half<<<(MM*DD/4 + 255)/256, 256>>>(E,  e_h,  MM*DD/4);
    cvt_half<<<(DD*DD/4 + 255)/256, 256>>>(WO, wo_h, DD*DD/4);

    // 1) Weff = HXcat @ WX (NN tf32), fp16 epilogue (z==0 scaled by QS)
    WBatch gw;
    gw.A[0] = HQ; gw.B[0] = WQ;
    gw.A[1] = HK; gw.B[1] = WK;
    gw.A[2] = HV; gw.B[2] = WV;
    gemm_nn_w<<<dim3(DD/128, DD/128, 3), 128>>>(gw, DD, DD, DD);

    // 2) q/k/v = E_h @ Weff^T (fp16 NT), fp16 out
    HBatch ga;
    for (int i = 0; i < 3; i++) {
        ga.A[i] = e_h;
        ga.B[i] = w_h + (size_t)i * DD * DD;
    }
    ga.C[0] = q_h; ga.C[1] = k_h; ga.C[2] = v_h;
    gemm_h<true><<<dim3(DD/128, MM/128, 3), 128>>>(ga, MM, DD, DD);

    // 3) attention (fp16 in, fp16 out)
    flash_h<<<dim3(SS/128, BB*HH), 128, FLASH_SMEM_BYTES>>>();

    // 4) out = O_h @ WO_h^T (fp16 NT), fp32 out
    HBatch go;
    for (int i = 0; i < 3; i++) {
        go.A[i] = o_h;
        go.B[i] = wo_h;
        go.C[i] = out;
    }
    gemm_h<false><<<dim3(DD/128, MM/128, 1), 128>>>(go, MM, DD, DD);
}

// round 17
// speedup vs baseline: 2.0100x; 1.0282x over previous
#include <cuda_runtime.h>
#include <cuda_fp16.h>
#include <cstdint>

#define BB 2
#define SS 2048
#define DD 1024
#define HH 16
#define EHD 64
#define MM (BB*SS)   // 4096

// fp16 operand buffers
__device__ __half g_e_h[MM*DD];
__device__ __half g_q_h[MM*DD];
__device__ __half g_k_h[MM*DD];
__device__ __half g_v_h[MM*DD];
__device__ __half g_o_h[MM*DD];
__device__ __half g_w_h[3*DD*DD];   // Weff q,k,v (q pre-scaled by QS)
__device__ __half g_wo_h[DD*DD];

#define QS 0.18033688f   // 0.125 * log2(e)  (exp2-domain softmax scale)

__device__ __forceinline__ uint32_t f2tf(float x) {
    uint32_t u; asm("cvt.rna.tf32.f32 %0, %1;" : "=r"(u) : "f"(x)); return u;
}

__device__ __forceinline__ uint32_t smem_u32(const void* p) {
    uint32_t a;
    asm("{ .reg .u64 t; cvta.to.shared.u64 t, %1; cvt.u32.u64 %0, t; }"
        : "=r"(a) : "l"(p));
    return a;
}

__device__ __forceinline__ void ldsm4(uint32_t* d, uint32_t addr) {
    asm volatile("ldmatrix.sync.aligned.m8n8.x4.shared.b16 {%0,%1,%2,%3}, [%4];"
        : "=r"(d[0]), "=r"(d[1]), "=r"(d[2]), "=r"(d[3]) : "r"(addr));
}
__device__ __forceinline__ void ldsm4t(uint32_t* d, uint32_t addr) {
    asm volatile("ldmatrix.sync.aligned.m8n8.x4.trans.shared.b16 {%0,%1,%2,%3}, [%4];"
        : "=r"(d[0]), "=r"(d[1]), "=r"(d[2]), "=r"(d[3]) : "r"(addr));
}

// tf32 m16n8k8 (weight GEMM only)
__device__ __forceinline__ void mma8(float* d, const uint32_t* a, const uint32_t* b) {
    asm volatile("mma.sync.aligned.m16n8k8.row.col.f32.tf32.tf32.f32 "
        "{%0,%1,%2,%3}, {%4,%5,%6,%7}, {%8,%9}, {%0,%1,%2,%3};\n"
        : "+f"(d[0]), "+f"(d[1]), "+f"(d[2]), "+f"(d[3])
        : "r"(a[0]), "r"(a[1]), "r"(a[2]), "r"(a[3]), "r"(b[0]), "r"(b[1]));
}

// fp16 m16n8k16, fp32 accumulate
__device__ __forceinline__ void mma16(float* d, const uint32_t* a, const uint32_t* b) {
    asm volatile("mma.sync.aligned.m16n8k16.row.col.f32.f16.f16.f32 "
        "{%0,%1,%2,%3}, {%4,%5,%6,%7}, {%8,%9}, {%0,%1,%2,%3};\n"
        : "+f"(d[0]), "+f"(d[1]), "+f"(d[2]), "+f"(d[3])
        : "r"(a[0]), "r"(a[1]), "r"(a[2]), "r"(a[3]), "r"(b[0]), "r"(b[1]));
}

__device__ __forceinline__ void cp_async16(uint32_t saddr, const void* gaddr) {
    asm volatile("cp.async.ca.shared.global [%0], [%1], 16;"
                 :: "r"(saddr), "l"(gaddr) : "memory");
}
__device__ __forceinline__ void cp_commit() {
    asm volatile("cp.async.commit_group;" ::: "memory");
}

__device__ __forceinline__ float ex2(float x) {
    float r; asm("ex2.approx.f32 %0, %1;" : "=f"(r) : "f"(x)); return r;
}

__device__ __forceinline__ uint32_t packh2(float a, float b) {
    __half2 h = __floats2half2_rn(a, b);
    return *(uint32_t*)&h;
}

// ---------------------------------------------------------------------------
// fp32 -> fp16 elementwise converter
// ---------------------------------------------------------------------------
__global__ void cvt_half(const float* __restrict__ s, __half* __restrict__ d, int n4)
{
    int i = blockIdx.x * blockDim.x + threadIdx.x;
    if (i < n4) {
        float4 v = ((const float4*)s)[i];
        __half2 h0 = __floats2half2_rn(v.x, v.y);
        __half2 h1 = __floats2half2_rn(v.z, v.w);
        uint2 u;
        u.x = *(uint32_t*)&h0;
        u.y = *(uint32_t*)&h1;
        ((uint2*)d)[i] = u;
    }
}

// ---------------------------------------------------------------------------
// Weight-prep GEMM (NN, tf32, proven): Weff = HXcat @ WX; fp16 epilogue,
// z==0 (Q weights) scaled by QS. 128 thr, warp tile 64x64, BK=16, 2-stage.
// ---------------------------------------------------------------------------
struct WBatch { const float* A[3]; const float* B[3]; };

__global__ __launch_bounds__(128) void gemm_nn_w(WBatch gb, int M, int N, int K)
{
    __shared__ uint32_t As[2][128][20];
    __shared__ uint32_t Bs[2][128][20];
    const float* __restrict__ A  = gb.A[blockIdx.z];
    const float* __restrict__ Bm = gb.B[blockIdx.z];
    __half* __restrict__ Ch = g_w_h + (size_t)blockIdx.z * DD * DD;
    const float csc = (blockIdx.z == 0) ? QS : 1.0f;

    const int tid  = threadIdx.x;
    const int lane = tid & 31, wid = tid >> 5;
    const int wm = wid & 1, wn = wid >> 1;
    const int m0 = blockIdx.y * 128, n0 = blockIdx.x * 128;
    const int r = lane >> 2, c = lane & 3;

    const int l15   = lane & 15;
    const int khalf = (lane >> 4) & 1;
    const int b_r   = (lane & 7) + ((lane & 16) >> 1);
    const int b_k4  = (lane & 8) >> 1;

    const uint32_t As_base = smem_u32(&As[0][0][0]);
    const uint32_t Bs_base = smem_u32(&Bs[0][0][0]);
    const uint32_t BUFB = 128 * 20 * 4;
    const uint32_t a_addr0 = As_base + (((wm * 64 + l15) * 20 + 4 * khalf) << 2);
    const uint32_t b_addr0 = Bs_base + (((wn * 64 + b_r) * 20 + b_k4) << 2);

    const int arow = tid >> 2, akq = (tid & 3) * 4;
    const int bkk  = tid & 15, bc4 = tid >> 4;

    float acc[4][8][4] = {};
    float4 pa[4], pb[4];

    auto ldg_tile = [&](int k0) {
#pragma unroll
        for (int i = 0; i < 4; i++)
            pa[i] = *(const float4*)&A[(size_t)(m0 + arow + 32 * i) * K + k0 + akq];
#pragma unroll
        for (int i = 0; i < 4; i++)
            pb[i] = *(const float4*)&Bm[(size_t)(k0 + bkk) * N + n0 + (bc4 + 8 * i) * 4];
    };
    auto sts_tile = [&](int buf) {
#pragma unroll
        for (int i = 0; i < 4; i++)
            *(uint4*)&As[buf][arow + 32 * i][akq] =
                make_uint4(f2tf(pa[i].x), f2tf(pa[i].y), f2tf(pa[i].z), f2tf(pa[i].w));
#pragma unroll
        for (int i = 0; i < 4; i++) {
            Bs[buf][(bc4 + 8 * i) * 4 + 0][bkk] = f2tf(pb[i].x);
            Bs[buf][(bc4 + 8 * i) * 4 + 1][bkk] = f2tf(pb[i].y);
            Bs[buf][(bc4 + 8 * i) * 4 + 2][bkk] = f2tf(pb[i].z);
            Bs[buf][(bc4 + 8 * i) * 4 + 3][bkk] = f2tf(pb[i].w);
        }
    };

    const int ntiles = K / 16;
    ldg_tile(0);
    sts_tile(0);
    if (ntiles > 1) ldg_tile(16);
    __syncthreads();

    for (int kt = 0; kt < ntiles; kt++) {
        const int buf = kt & 1;
        if (kt + 1 < ntiles) {
            sts_tile(buf ^ 1);
            if (kt + 2 < ntiles) ldg_tile((kt + 2) * 16);
        }

        const uint32_t aoff = buf ? BUFB : 0;
#pragma unroll
        for (int ks = 0; ks < 2; ks++) {
            uint32_t af[4][4], bf[4][4];
#pragma unroll
            for (int mi = 0; mi < 4; mi++)
                ldsm4(af[mi], a_addr0 + aoff + ((mi * 16 * 20 + ks * 8) << 2));
#pragma unroll
            for (int nj = 0; nj < 4; nj++)
                ldsm4(bf[nj], b_addr0 + aoff + ((nj * 16 * 20 + ks * 8) << 2));
#pragma unroll
            for (int mi = 0; mi < 4; mi++)
#pragma unroll
                for (int ni = 0; ni < 8; ni++)
                    mma8(acc[mi][ni], af[mi], &bf[ni >> 1][(ni & 1) * 2]);
        }
        __syncthreads();
    }

#pragma unroll
    for (int mi = 0; mi < 4; mi++)
#pragma unroll
        for (int ni = 0; ni < 8; ni++) {
            int row = m0 + wm * 64 + mi * 16 + r;
            int col = n0 + wn * 64 + ni * 8 + 2 * c;
            *(__half2*)&Ch[(size_t)row * N + col] =
                __floats2half2_rn(acc[mi][ni][0] * csc, acc[mi][ni][1] * csc);
            *(__half2*)&Ch[(size_t)(row + 8) * N + col] =
                __floats2half2_rn(acc[mi][ni][2] * csc, acc[mi][ni][3] * csc);
        }
}

// ---------------------------------------------------------------------------
// fp16 NT GEMM (R15-proven): C = A[M,K] @ B[N,K]^T, fp32 accum.
// 128 thr, warp tile 64x64, CTA 128x128, BK=16, 3-stage cp.async ring.
// ---------------------------------------------------------------------------
struct HBatch { const __half* A[3]; const __half* B[3]; void* C[3]; };

template<bool HALF_OUT>
__global__ __launch_bounds__(128, 2) void gemm_h(HBatch gb, int M, int N, int K)
{
    __shared__ __align__(16) __half As[3][128][24];
    __shared__ __align__(16) __half Bs[3][128][24];
    const __half* __restrict__ A  = gb.A[blockIdx.z];
    const __half* __restrict__ Bm = gb.B[blockIdx.z];

    const int tid  = threadIdx.x;
    const int lane = tid & 31, wid = tid >> 5;
    const int wm = wid & 1, wn = wid >> 1;
    const int m0 = blockIdx.y * 128, n0 = blockIdx.x * 128;
    const int r = lane >> 2, c = lane & 3;

    const int l15   = lane & 15;
    const int khalf = (lane >> 4) & 1;
    const int b_r   = (lane & 7) + ((lane & 16) >> 1);
    const int b_kh  = (lane >> 3) & 1;

    const uint32_t Ab = smem_u32(&As[0][0][0]);
    const uint32_t Bb = smem_u32(&Bs[0][0][0]);
    const uint32_t STG = 128 * 48;
    const uint32_t a0 = Ab + (wm * 64 + l15) * 48 + khalf * 16;
    const uint32_t b0 = Bb + (wn * 64 + b_r) * 48 + b_kh * 16;

    const __half* gA = A  + (size_t)(m0 + tid) * K;
    const __half* gB = Bm + (size_t)(n0 + tid) * K;
    auto issue = [&](int kt) {
        const uint32_t s = (uint32_t)(kt % 3) * STG;
        const int k0 = kt * 16;
        cp_async16(Ab + s + tid * 48,      gA + k0);
        cp_async16(Ab + s + tid * 48 + 16, gA + k0 + 8);
        cp_async16(Bb + s + tid * 48,      gB + k0);
        cp_async16(Bb + s + tid * 48 + 16, gB + k0 + 8);
        cp_commit();
    };

    float acc[4][8][4] = {};
    const int ntiles = K / 16;
    issue(0); issue(1); issue(2);

    for (int kt = 0; kt < ntiles; kt++) {
        const uint32_t s = (uint32_t)(kt % 3) * STG;
        asm volatile("cp.async.wait_group 2;" ::: "memory");
        __syncthreads();

        uint32_t af[4][4], bf[4][4];
#pragma unroll
        for (int mi = 0; mi < 4; mi++)
            ldsm4(af[mi], a0 + s + mi * 16 * 48);
#pragma unroll
        for (int nj = 0; nj < 4; nj++)
            ldsm4(bf[nj], b0 + s + nj * 16 * 48);
#pragma unroll
        for (int mi = 0; mi < 4; mi++)
#pragma unroll
            for (int ni = 0; ni < 8; ni++)
                mma16(acc[mi][ni], af[mi], &bf[ni >> 1][(ni & 1) * 2]);

        __syncthreads();
        if (kt + 3 < ntiles) issue(kt + 3);
        else cp_commit();
    }

#pragma unroll
    for (int mi = 0; mi < 4; mi++)
#pragma unroll
        for (int ni = 0; ni < 8; ni++) {
            int row = m0 + wm * 64 + mi * 16 + r;
            int col = n0 + wn * 64 + ni * 8 + 2 * c;
            if (HALF_OUT) {
                __half* Ch = (__half*)gb.C[blockIdx.z];
                *(__half2*)&Ch[(size_t)row * N + col] =
                    __floats2half2_rn(acc[mi][ni][0], acc[mi][ni][1]);
                *(__half2*)&Ch[(size_t)(row + 8) * N + col] =
                    __floats2half2_rn(acc[mi][ni][2], acc[mi][ni][3]);
            } else {
                float* Cf = (float*)gb.C[blockIdx.z];
                *(float2*)&Cf[(size_t)row * N + col] =
                    make_float2(acc[mi][ni][0], acc[mi][ni][1]);
                *(float2*)&Cf[(size_t)(row + 8) * N + col] =
                    make_float2(acc[mi][ni][2], acc[mi][ni][3]);
            }
        }
}

// ---------------------------------------------------------------------------
// fp16 flash attention, key tile 64, exp2 softmax, P KEPT IN REGISTERS:
// the m16n8k16 C-fragment layout of S == A-fragment layout of PV, so the
// exp'd scores are packed to half2 pairs and fed straight to the PV mma.
// No P smem region, no syncwarp. V B-frags via ldmatrix.trans.
// smem (halves): Ks[2][64][72] @0, Vs[2][64][72] @9216 -> 36,864 B.
// ---------------------------------------------------------------------------
#define F_VS 9216
#define FLASH_SMEM_BYTES ((F_VS + 2*64*72) * 2)

__global__ __launch_bounds__(128, 2) void flash_h()
{
    extern __shared__ __align__(16) __half hsm[];

    const int tid  = threadIdx.x;
    const int lane = tid & 31, w = tid >> 5;
    const int r = lane >> 2, c = lane & 3;
    const int s0 = blockIdx.x * 128;
    const int bh = blockIdx.y;
    const int h = bh & (HH - 1), b = bh / HH;

    const int b_r   = (lane & 7) + ((lane & 16) >> 1);
    const int b_kh  = (lane >> 3) & 1;
    const int vrow  = (lane & 7) + ((lane & 8) ? 8 : 0);
    const int veoff = (lane >> 4) & 1;

    const uint32_t base = smem_u32(hsm);
    const uint32_t ksb = base;
    const uint32_t vsb = base + F_VS * 2;

    const uint32_t ks_lane = ksb + b_r * 144 + b_kh * 16;
    const uint32_t vs_lane = vsb + vrow * 144 + veoff * 16;

    // Q fragments (fp16, already QS-scaled): 2 m-tiles x 4 k16-tiles
    uint32_t qa[2][4][4];
#pragma unroll
    for (int mi = 0; mi < 2; mi++) {
        const __half* qp = g_q_h + (size_t)(b * SS + s0 + w * 32 + mi * 16) * DD + h * EHD;
#pragma unroll
        for (int kt = 0; kt < 4; kt++) {
            qa[mi][kt][0] = *(const uint32_t*)&qp[(size_t)r       * DD + kt * 16 + 2 * c];
            qa[mi][kt][1] = *(const uint32_t*)&qp[(size_t)(r + 8) * DD + kt * 16 + 2 * c];
            qa[mi][kt][2] = *(const uint32_t*)&qp[(size_t)r       * DD + kt * 16 + 8 + 2 * c];
            qa[mi][kt][3] = *(const uint32_t*)&qp[(size_t)(r + 8) * DD + kt * 16 + 8 + 2 * c];
        }
    }

    // cp.async K/V loader: thread t: row t>>1, half (t&1) of the 128B row
    const int krow = tid >> 1, hf = tid & 1;
    auto cp_kv = [&](int t0, int buf) {
        const size_t g = (size_t)(b * SS + t0 + krow) * DD + h * EHD + hf * 32;
        const uint32_t d = (uint32_t)buf * 9216 + krow * 144 + hf * 64;
#pragma unroll
        for (int j = 0; j < 4; j++) {
            cp_async16(ksb + d + j * 16, g_k_h + g + j * 8);
            cp_async16(vsb + d + j * 16, g_v_h + g + j * 8);
        }
        cp_commit();
    };

    float o[2][8][4] = {};
    float mv[2][2], lv[2][2];
#pragma unroll
    for (int mi = 0; mi < 2; mi++) { mv[mi][0] = mv[mi][1] = -1e30f; lv[mi][0] = lv[mi][1] = 0.f; }

    const int NT = SS / 64;
    cp_kv(0, 0);
    cp_kv(64, 1);

    for (int ti = 0; ti < NT; ti++) {
        const int buf = ti & 1;
        asm volatile("cp.async.wait_group 1;" ::: "memory");
        __syncthreads();

        const uint32_t koff = (uint32_t)buf * 9216;

        // S = Q K^T : 32x64 per warp; 4 k16-steps x 8 n-tiles x 2 m
        float sc[2][8][4] = {};
#pragma unroll
        for (int kst = 0; kst < 4; kst++) {
            uint32_t kb[4][4];
#pragma unroll
            for (int j = 0; j < 4; j++)
                ldsm4(kb[j], ks_lane + koff + j * 16 * 144 + kst * 32);
#pragma unroll
            for (int nt = 0; nt < 8; nt++) {
                mma16(sc[0][nt], qa[0][kst], &kb[nt >> 1][(nt & 1) * 2]);
                mma16(sc[1][nt], qa[1][kst], &kb[nt >> 1][(nt & 1) * 2]);
            }
        }

        // online softmax (log2 domain); pack P into A-fragment half2 regs
        bool need_rescale = false;
        float cor[2][2];
        uint32_t ph[2][8][2];
#pragma unroll
        for (int mi = 0; mi < 2; mi++) {
            float t0m = -1e30f, t1m = -1e30f;
#pragma unroll
            for (int nt = 0; nt < 8; nt++) {
                t0m = fmaxf(t0m, fmaxf(sc[mi][nt][0], sc[mi][nt][1]));
                t1m = fmaxf(t1m, fmaxf(sc[mi][nt][2], sc[mi][nt][3]));
            }
            t0m = fmaxf(t0m, __shfl_xor_sync(0xffffffff, t0m, 1));
            t0m = fmaxf(t0m, __shfl_xor_sync(0xffffffff, t0m, 2));
            t1m = fmaxf(t1m, __shfl_xor_sync(0xffffffff, t1m, 1));
            t1m = fmaxf(t1m, __shfl_xor_sync(0xffffffff, t1m, 2));

            float mn0 = fmaxf(mv[mi][0], t0m), mn1 = fmaxf(mv[mi][1], t1m);
            cor[mi][0] = ex2(mv[mi][0] - mn0);
            cor[mi][1] = ex2(mv[mi][1] - mn1);
            need_rescale |= (mn0 > mv[mi][0]) || (mn1 > mv[mi][1]);
            mv[mi][0] = mn0; mv[mi][1] = mn1;

            float ps0 = 0.f, ps1 = 0.f;
#pragma unroll
            for (int nt = 0; nt < 8; nt++) {
                float p0 = ex2(sc[mi][nt][0] - mn0);
                float p1 = ex2(sc[mi][nt][1] - mn0);
                float p2 = ex2(sc[mi][nt][2] - mn1);
                float p3 = ex2(sc[mi][nt][3] - mn1);
                ps0 += p0 + p1; ps1 += p2 + p3;
                ph[mi][nt][0] = packh2(p0, p1);   // rows r   (a0/a2 slots)
                ph[mi][nt][1] = packh2(p2, p3);   // rows r+8 (a1/a3 slots)
            }
            ps0 += __shfl_xor_sync(0xffffffff, ps0, 1);
            ps0 += __shfl_xor_sync(0xffffffff, ps0, 2);
            ps1 += __shfl_xor_sync(0xffffffff, ps1, 1);
            ps1 += __shfl_xor_sync(0xffffffff, ps1, 2);
            lv[mi][0] = lv[mi][0] * cor[mi][0] + ps0;
            lv[mi][1] = lv[mi][1] * cor[mi][1] + ps1;
        }

        if (__ballot_sync(0xffffffff, need_rescale)) {
#pragma unroll
            for (int mi = 0; mi < 2; mi++)
#pragma unroll
                for (int ne = 0; ne < 8; ne++) {
                    o[mi][ne][0] *= cor[mi][0]; o[mi][ne][1] *= cor[mi][0];
                    o[mi][ne][2] *= cor[mi][1]; o[mi][ne][3] *= cor[mi][1];
                }
        }

        // O += P V : 4 key16-steps; P A-frags from registers, V via LDSM.trans
#pragma unroll
        for (int k2 = 0; k2 < 4; k2++) {
            uint32_t pa0[4], pa1[4];
            pa0[0] = ph[0][2 * k2][0];     pa0[1] = ph[0][2 * k2][1];
            pa0[2] = ph[0][2 * k2 + 1][0]; pa0[3] = ph[0][2 * k2 + 1][1];
            pa1[0] = ph[1][2 * k2][0];     pa1[1] = ph[1][2 * k2][1];
            pa1[2] = ph[1][2 * k2 + 1][0]; pa1[3] = ph[1][2 * k2 + 1][1];
            uint32_t vb[4][4];
#pragma unroll
            for (int ne = 0; ne < 4; ne++)
                ldsm4t(vb[ne], vs_lane + koff + k2 * 16 * 144 + ne * 32);
#pragma unroll
            for (int ne = 0; ne < 8; ne++) {
                mma16(o[0][ne], pa0, &vb[ne >> 1][(ne & 1) * 2]);
                mma16(o[1][ne], pa1, &vb[ne >> 1][(ne & 1) * 2]);
            }
        }

        __syncthreads();
        if (ti + 2 < NT) cp_kv((ti + 2) * 64, buf);
    }

    // epilogue: O -> fp16
#pragma unroll
    for (int mi = 0; mi < 2; mi++) {
        const float inv0 = 1.f / lv[mi][0], inv1 = 1.f / lv[mi][1];
        const size_t ob = (size_t)(b * SS + s0 + w * 32 + mi * 16) * DD + h * EHD;
#pragma unroll
        for (int ne = 0; ne < 8; ne++) {
            const int col = ne * 8 + 2 * c;
            *(__half2*)&g_o_h[ob + (size_t)r * DD + col] =
                __floats2half2_rn(o[mi][ne][0] * inv0, o[mi][ne][1] * inv0);
            *(__half2*)&g_o_h[ob + (size_t)(r + 8) * DD + col] =
                __floats2half2_rn(o[mi][ne][2] * inv1, o[mi][ne][3] * inv1);
        }
    }
}

// ---------------------------------------------------------------------------
extern "C" void kernel_launch(void* const* d_in, const int* in_sizes, int n_in,
                              void* d_out, int out_size)
{
    (void)in_sizes; (void)n_in; (void)out_size;
    const float* E  = (const float*)d_in[0];
    const float* WQ = (const float*)d_in[1];
    const float* WK = (const float*)d_in[2];
    const float* WV = (const float*)d_in[3];
    const float* WO = (const float*)d_in[4];
    const float* HQ = (const float*)d_in[5];
    const float* HK = (const float*)d_in[6];
    const float* HV = (const float*)d_in[7];
    float* out = (float*)d_out;

    __half *e_h, *q_h, *k_h, *v_h, *o_h, *w_h, *wo_h;
    cudaGetSymbolAddress((void**)&e_h,  g_e_h);
    cudaGetSymbolAddress((void**)&q_h,  g_q_h);
    cudaGetSymbolAddress((void**)&k_h,  g_k_h);
    cudaGetSymbolAddress((void**)&v_h,  g_v_h);
    cudaGetSymbolAddress((void**)&o_h,  g_o_h);
    cudaGetSymbolAddress((void**)&w_h,  g_w_h);
    cudaGetSymbolAddress((void**)&wo_h, g_wo_h);

    cudaFuncSetAttribute(flash_h, cudaFuncAttributeMaxDynamicSharedMemorySize,
                         FLASH_SMEM_BYTES);

    // 0) convert E and WO to fp16
    cvt_half<<<(MM*DD/4 + 255)/256, 256>>>(E,  e_h,  MM*DD/4);
    cvt_half<<<(DD*DD/4 + 255)/256, 256>>>(WO, wo_h, DD*DD/4);

    // 1) Weff = HXcat @ WX (NN tf32), fp16 epilogue (z==0 scaled by QS)
    WBatch gw;
    gw.A[0] = HQ; gw.B[0] = WQ;
    gw.A[1] = HK; gw.B[1] = WK;
    gw.A[2] = HV; gw.B[2] = WV;
    gemm_nn_w<<<dim3(DD/128, DD/128, 3), 128>>>(gw, DD, DD, DD);

    // 2) q/k/v = E_h @ Weff^T (fp16 NT), fp16 out
    HBatch ga;
    for (int i = 0; i < 3; i++) {
        ga.A[i] = e_h;
        ga.B[i] = w_h + (size_t)i * DD * DD;
    }
    ga.C[0] = q_h; ga.C[1] = k_h; ga.C[2] = v_h;
    gemm_h<true><<<dim3(DD/128, MM/128, 3), 128>>>(ga, MM, DD, DD);

    // 3) attention (fp16 in, fp16 out; P register-resident)
    flash_h<<<dim3(SS/128, BB*HH), 128, FLASH_SMEM_BYTES>>>();

    // 4) out = O_h @ WO_h^T (fp16 NT), fp32 out
    HBatch go;
    for (int i = 0; i < 3; i++) {
        go.A[i] = o_h;
        go.B[i] = wo_h;
        go.C[i] = out;
    }
    gemm_h<false><<<dim3(DD/128, MM/128, 1), 128>>>(go, MM, DD, DD);
}